// round 1
// baseline (speedup 1.0000x reference)
#include <cuda_runtime.h>
#include <math.h>

// ---- problem constants ----
#define N_IMG 5
#define C_CH  256
#define HH    128
#define WWID  128
#define HW    16384
#define NP    81920            // N_IMG * HW
#define C4    1024             // 4*C
#define C2    512              // 2*C
#define THRE  0.01f

// output layout: [sparse_feature (20971520) | loss (1) | rate (1) | sparse_mask (20971520)]
#define SF_ELEMS 20971520
#define LOSS_IDX 20971520
#define RATE_IDX 20971521
#define SM_OFF   20971522

// gaussian2d (unnormalized, 1/(2*pi*sigma) * exp(-(r^2)/2))
#define G2_C 0.15915494309189535f
#define G2_E 0.09653235263005391f
#define G2_D 0.05855018091964769f
// gaussian1d (normalized)
#define G1_C 0.45186276187760605f
#define G1_S 0.27406861906119697f

// ---- device scratch (no allocation allowed) ----
__device__ float g_U[(size_t)NP * C4];   // layer1 feat part   [P][j]
__device__ float g_V[(size_t)NP * C4];   // layer1 sparse part [P][j]
__device__ float g_avg[N_IMG * C_CH];
__device__ float g_mx[N_IMG * C_CH];
__device__ float g_chatt[N_IMG * C_CH];
__device__ float g_chcoef[4 * C_CH];
__device__ float g_cmean[NP];
__device__ float g_cmax[NP];
__device__ float g_spatt[NP];
__device__ float g_act[NP];
__device__ float g_spcoef[4 * HW];
__device__ float g_tT[NP];
__device__ float g_tP[NP];
__device__ unsigned long long g_cnt;

__device__ __forceinline__ float sigmoidf(float x) { return 1.f / (1.f + expf(-x)); }
__device__ __forceinline__ float softplusf(float x) { return fmaxf(x, 0.f) + log1pf(expf(-fabsf(x))); }
__device__ __forceinline__ float g2w(int ky, int kx) {
    int d = (ky != 1) + (kx != 1);
    return d == 0 ? G2_C : (d == 1 ? G2_E : G2_D);
}

// ------------------------------------------------------------------
// init: zero accumulators
__global__ void init_kernel() {
    int i = blockIdx.x * blockDim.x + threadIdx.x;
    if (i < NP) { g_tT[i] = 0.f; g_tP[i] = 0.f; }
    if (i == 0) g_cnt = 0ULL;
}

// ------------------------------------------------------------------
// per-(n,c) mean and max over HW
__global__ void reduce_nc_kernel(const float* __restrict__ feat) {
    int nc = blockIdx.x;                 // 0..1279
    const float* base = feat + (size_t)nc * HW;
    int t = threadIdx.x;
    float s = 0.f, m = -3.402823466e38f;
    for (int i = t; i < HW; i += 256) {
        float v = base[i];
        s += v; m = fmaxf(m, v);
    }
    __shared__ float ss[256], sm[256];
    ss[t] = s; sm[t] = m;
    __syncthreads();
    for (int st = 128; st > 0; st >>= 1) {
        if (t < st) { ss[t] += ss[t + st]; sm[t] = fmaxf(sm[t], sm[t + st]); }
        __syncthreads();
    }
    if (t == 0) { g_avg[nc] = ss[0] * (1.f / HW); g_mx[nc] = sm[0]; }
}

// per-pixel mean and max over channels
__global__ void reduce_pix_kernel(const float* __restrict__ feat) {
    int p = blockIdx.x * blockDim.x + threadIdx.x;   // 0..NP-1
    if (p >= NP) return;
    int n = p >> 14, pix = p & 16383;
    const float* base = feat + (size_t)n * C_CH * HW + pix;
    float s = 0.f, m = -3.402823466e38f;
    #pragma unroll 8
    for (int c = 0; c < C_CH; c++) {
        float v = base[(size_t)c * HW];
        s += v; m = fmaxf(m, v);
    }
    g_cmean[p] = s * (1.f / C_CH);
    g_cmax[p] = m;
}

// ------------------------------------------------------------------
// channel attention: ch_att = sigmoid(mlp(avg)+mlp(mx)), single block
__global__ void chatt_kernel(const float* __restrict__ w1, const float* __restrict__ w2) {
    __shared__ float hs[N_IMG][16];
    int t = threadIdx.x;
    if (t < N_IMG * 16) {
        int n = t / 16, h = t % 16;
        float sa = 0.f, sm = 0.f;
        const float* wr = w1 + h * C_CH;
        const float* av = g_avg + n * C_CH;
        const float* mv = g_mx + n * C_CH;
        for (int c = 0; c < C_CH; c++) { sa += av[c] * wr[c]; sm += mv[c] * wr[c]; }
        hs[n][h] = fmaxf(sa, 0.f) + fmaxf(sm, 0.f);
    }
    __syncthreads();
    for (int idx = t; idx < N_IMG * C_CH; idx += 256) {
        int n = idx >> 8, c = idx & 255;
        float p = 0.f;
        #pragma unroll
        for (int h = 0; h < 16; h++) p += hs[n][h] * w2[c * 16 + h];
        g_chatt[idx] = sigmoidf(p);
    }
}

// ------------------------------------------------------------------
// spatial: sp_att = sigmoid(conv3x3([cmean,cmax], sp_req_w)); act = conv3x3(sigmoid(cmean), g2)
__global__ void spatial_kernel(const float* __restrict__ sw) {
    int idx = blockIdx.x * blockDim.x + threadIdx.x;
    if (idx >= NP) return;
    int n = idx >> 14, pix = idx & 16383;
    int h = pix >> 7, w = pix & 127;
    float satt = 0.f, act = 0.f;
    #pragma unroll
    for (int ky = 0; ky < 3; ky++) {
        int hh = h + ky - 1;
        if (hh < 0 || hh >= HH) continue;
        #pragma unroll
        for (int kx = 0; kx < 3; kx++) {
            int ww = w + kx - 1;
            if (ww < 0 || ww >= WWID) continue;
            int q = n * HW + hh * WWID + ww;
            float cm = g_cmean[q], cx = g_cmax[q];
            satt += cm * sw[ky * 3 + kx] + cx * sw[9 + ky * 3 + kx];
            act += g2w(ky, kx) * sigmoidf(cm);
        }
    }
    g_spatt[idx] = sigmoidf(satt);
    g_act[idx] = act;
}

// ------------------------------------------------------------------
// ch_coef: sigmoid(ego_ch@Wa^T + ch_att[1:]@Wb^T) then gaussian1d over c; single block
__global__ void chcoef_kernel(const float* __restrict__ cfw) {
    __shared__ float ego[C_CH];
    __shared__ float att[4][C_CH];
    __shared__ float tmp[4][C_CH];
    int t = threadIdx.x;
    for (int i = t; i < C_CH; i += 256) ego[i] = 1.f - g_chatt[i];
    for (int i = t; i < 4 * C_CH; i += 256) att[i >> 8][i & 255] = g_chatt[C_CH + i];
    __syncthreads();
    for (int i = t; i < 4 * C_CH; i += 256) {
        int n = i >> 8, c = i & 255;
        const float* row = cfw + (size_t)c * C2;
        float p = 0.f;
        for (int k = 0; k < C_CH; k++) p += ego[k] * row[k] + att[n][k] * row[C_CH + k];
        tmp[n][c] = sigmoidf(p);
    }
    __syncthreads();
    for (int i = t; i < 4 * C_CH; i += 256) {
        int n = i >> 8, c = i & 255;
        float v = G1_C * tmp[n][c];
        if (c > 0)   v += G1_S * tmp[n][c - 1];
        if (c < 255) v += G1_S * tmp[n][c + 1];
        g_chcoef[i] = v;
    }
}

// ------------------------------------------------------------------
// sp_coef: conv3x3(sigmoid(wa*ego_sp + wb*sp_att[1:]), g2)
__global__ void spcoef_kernel(const float* __restrict__ spfus) {
    int idx = blockIdx.x * blockDim.x + threadIdx.x;
    if (idx >= 4 * HW) return;
    int m = idx >> 14, pix = idx & 16383;
    int h = pix >> 7, w = pix & 127;
    float wa = spfus[0], wb = spfus[1];
    float acc = 0.f;
    #pragma unroll
    for (int ky = 0; ky < 3; ky++) {
        int hh = h + ky - 1;
        if (hh < 0 || hh >= HH) continue;
        #pragma unroll
        for (int kx = 0; kx < 3; kx++) {
            int ww = w + kx - 1;
            if (ww < 0 || ww >= WWID) continue;
            int q = hh * WWID + ww;
            float pre = wa * (1.f - g_spatt[q]) + wb * g_spatt[(m + 1) * HW + q];
            acc += g2w(ky, kx) * sigmoidf(pre);
        }
    }
    g_spcoef[idx] = acc;
}

// ------------------------------------------------------------------
// mask + sparse_feature + sparse_mask + mask count
__global__ void mask_kernel(const float* __restrict__ feat,
                            float* __restrict__ out_sf, float* __restrict__ out_sm) {
    int t = threadIdx.x;
    unsigned int cnt = 0;
    const int total = N_IMG * C_CH * HW;
    for (int idx = blockIdx.x * blockDim.x + t; idx < total; idx += gridDim.x * blockDim.x) {
        int n = idx / (C_CH * HW);
        float f = feat[idx];
        float sf, sm;
        if (n == 0) { sf = f; sm = 1.f; }
        else {
            int rem = idx - n * C_CH * HW;
            int c = rem >> 14, p = rem & 16383;
            int m = n - 1;
            float v = g_chcoef[m * C_CH + c] * g_spcoef[m * HW + p] * g_act[n * HW + p];
            bool mk = v > THRE;
            sf = mk ? f : 0.f; sm = mk ? 1.f : 0.f;
            cnt += mk ? 1u : 0u;
        }
        out_sf[idx] = sf;
        out_sm[idx] = sm;
    }
    __shared__ unsigned int sc[256];
    sc[t] = cnt;
    __syncthreads();
    for (int s = 128; s > 0; s >>= 1) { if (t < s) sc[t] += sc[t + s]; __syncthreads(); }
    if (t == 0) atomicAdd(&g_cnt, (unsigned long long)sc[0]);
}

// ------------------------------------------------------------------
// GEMM1: Out[P][j] = sum_c A[n][c][p] * W[j][wcol+c]   (M=81920, N=1024, K=256)
// which==0 -> g_U, which==1 -> g_V
__global__ __launch_bounds__(256) void gemm1_kernel(const float* __restrict__ A,
                                                    const float* __restrict__ W,
                                                    int wcol, int which) {
    __shared__ __align__(16) float As[16][128];
    __shared__ __align__(16) float Bs[64][17];
    float* Out = which ? g_V : g_U;
    int ob = blockIdx.x;                 // 0..15
    int P0 = blockIdx.y * 128;           // pixel tile
    int n = P0 >> 14, p0 = P0 & 16383;
    int o0 = ob * 64;
    int t = threadIdx.x;
    int tx = t & 15, ty = t >> 4;
    const float* Abase = A + (size_t)n * C_CH * HW + p0;
    float acc[8][4] = {};
    for (int k0 = 0; k0 < 256; k0 += 16) {
        #pragma unroll
        for (int r = 0; r < 8; r++) {
            int i = t + 256 * r;
            int kk = i >> 7, pp = i & 127;
            As[kk][pp] = Abase[(size_t)(k0 + kk) * HW + pp];
        }
        #pragma unroll
        for (int r = 0; r < 4; r++) {
            int i = t + 256 * r;
            int jj = i >> 4, kk = i & 15;
            Bs[jj][kk] = W[(size_t)(o0 + jj) * C2 + wcol + k0 + kk];
        }
        __syncthreads();
        #pragma unroll
        for (int kk = 0; kk < 16; kk++) {
            float4 a0 = *(const float4*)&As[kk][ty * 8];
            float4 a1 = *(const float4*)&As[kk][ty * 8 + 4];
            float a[8] = {a0.x, a0.y, a0.z, a0.w, a1.x, a1.y, a1.z, a1.w};
            float b[4];
            #pragma unroll
            for (int j = 0; j < 4; j++) b[j] = Bs[tx * 4 + j][kk];
            #pragma unroll
            for (int i = 0; i < 8; i++)
                #pragma unroll
                for (int j = 0; j < 4; j++)
                    acc[i][j] += a[i] * b[j];
        }
        __syncthreads();
    }
    #pragma unroll
    for (int i = 0; i < 8; i++) {
        float4 v = make_float4(acc[i][0], acc[i][1], acc[i][2], acc[i][3]);
        *(float4*)&Out[(size_t)(P0 + ty * 8 + i) * C4 + o0 + tx * 4] = v;
    }
}

// ------------------------------------------------------------------
// GEMM2 fused: z = relu(U[rolled] + V + b1); acc = z @ W2^T; epilogue relu+b2, dot w3 -> atomic t
__global__ __launch_bounds__(256) void gemm2_kernel(const float* __restrict__ b1,
                                                    const float* __restrict__ W2,
                                                    const float* __restrict__ b2,
                                                    const float* __restrict__ w3,
                                                    int roll) {
    __shared__ __align__(16) float As[16][128];
    __shared__ __align__(16) float Bs[64][17];
    __shared__ float sRed[128][17];
    float* tOut = roll ? g_tP : g_tT;
    int o0 = blockIdx.x * 64;            // 0..15 tiles
    int P0 = blockIdx.y * 128;
    int n = P0 >> 14, p0 = P0 & 16383;
    int nu = roll ? ((n + 1 == N_IMG) ? 0 : n + 1) : n;
    const float* Ubase = g_U + ((size_t)nu * HW + p0) * C4;
    const float* Vbase = g_V + ((size_t)n * HW + p0) * C4;
    int t = threadIdx.x;
    int tx = t & 15, ty = t >> 4;
    float acc[8][4] = {};
    for (int k0 = 0; k0 < C4; k0 += 16) {
        #pragma unroll
        for (int r = 0; r < 8; r++) {
            int i = t + 256 * r;
            int pp = i >> 4, kk = i & 15;
            int k = k0 + kk;
            float z = Ubase[(size_t)pp * C4 + k] + Vbase[(size_t)pp * C4 + k] + b1[k];
            As[kk][pp] = fmaxf(z, 0.f);
        }
        #pragma unroll
        for (int r = 0; r < 4; r++) {
            int i = t + 256 * r;
            int jj = i >> 4, kk = i & 15;
            Bs[jj][kk] = W2[(size_t)(o0 + jj) * C4 + k0 + kk];
        }
        __syncthreads();
        #pragma unroll
        for (int kk = 0; kk < 16; kk++) {
            float4 a0 = *(const float4*)&As[kk][ty * 8];
            float4 a1 = *(const float4*)&As[kk][ty * 8 + 4];
            float a[8] = {a0.x, a0.y, a0.z, a0.w, a1.x, a1.y, a1.z, a1.w};
            float b[4];
            #pragma unroll
            for (int j = 0; j < 4; j++) b[j] = Bs[tx * 4 + j][kk];
            #pragma unroll
            for (int i = 0; i < 8; i++)
                #pragma unroll
                for (int j = 0; j < 4; j++)
                    acc[i][j] += a[i] * b[j];
        }
        __syncthreads();
    }
    // epilogue: relu(+b2) * w3, reduce over o-tile, atomic into t
    #pragma unroll
    for (int i = 0; i < 8; i++) {
        float s = 0.f;
        #pragma unroll
        for (int j = 0; j < 4; j++) {
            int o = o0 + tx * 4 + j;
            float h = fmaxf(acc[i][j] + b2[o], 0.f);
            s += h * w3[o];
        }
        sRed[ty * 8 + i][tx] = s;
    }
    __syncthreads();
    if (t < 128) {
        float s = 0.f;
        #pragma unroll
        for (int x = 0; x < 16; x++) s += sRed[t][x];
        atomicAdd(&tOut[P0 + t], s);
    }
}

// ------------------------------------------------------------------
// final loss + rate
__global__ void loss_kernel(const float* __restrict__ st_b3, float* __restrict__ out) {
    __shared__ double red[256];
    int t = threadIdx.x;
    float b3 = st_b3[0];
    double s = 0.0;
    for (int i = t; i < NP; i += 256) {
        float tt = g_tT[i] + b3;
        float tp = g_tP[i] + b3;
        s += (double)softplusf(-tt) + (double)softplusf(tp);
    }
    red[t] = s;
    __syncthreads();
    for (int st = 128; st > 0; st >>= 1) { if (t < st) red[t] += red[t + st]; __syncthreads(); }
    if (t == 0) {
        out[LOSS_IDX] = (float)(red[0] / 81920.0);
        out[RATE_IDX] = (float)((double)g_cnt / 16777216.0);
    }
}

// ------------------------------------------------------------------
extern "C" void kernel_launch(void* const* d_in, const int* in_sizes, int n_in,
                              void* d_out, int out_size) {
    const float* feat     = (const float*)d_in[0];
    const float* mlp_w1   = (const float*)d_in[1];
    const float* mlp_w2   = (const float*)d_in[2];
    const float* sp_req_w = (const float*)d_in[3];
    const float* ch_fus_w = (const float*)d_in[4];
    const float* sp_fus_w = (const float*)d_in[5];
    const float* st_w1    = (const float*)d_in[6];
    const float* st_b1    = (const float*)d_in[7];
    const float* st_w2    = (const float*)d_in[8];
    const float* st_b2    = (const float*)d_in[9];
    const float* st_w3    = (const float*)d_in[10];
    const float* st_b3    = (const float*)d_in[11];

    float* out = (float*)d_out;
    float* out_sf = out;            // sparse_feature at offset 0
    float* out_sm = out + SM_OFF;   // sparse_mask

    init_kernel<<<(NP + 255) / 256, 256>>>();
    reduce_nc_kernel<<<N_IMG * C_CH, 256>>>(feat);
    reduce_pix_kernel<<<(NP + 255) / 256, 256>>>(feat);
    chatt_kernel<<<1, 256>>>(mlp_w1, mlp_w2);
    spatial_kernel<<<(NP + 255) / 256, 256>>>(sp_req_w);
    chcoef_kernel<<<1, 256>>>(ch_fus_w);
    spcoef_kernel<<<(4 * HW + 255) / 256, 256>>>(sp_fus_w);
    mask_kernel<<<2048, 256>>>(feat, out_sf, out_sm);

    // layer1: U from feat (W1 cols 0..255), V from sparse_feature (W1 cols 256..511)
    dim3 g1grid(16, NP / 128);
    gemm1_kernel<<<g1grid, 256>>>(feat, st_w1, 0, 0);
    gemm1_kernel<<<g1grid, 256>>>(out_sf, st_w1, C_CH, 1);

    // layer2 + layer3 fused, two branches
    dim3 g2grid(16, NP / 128);
    gemm2_kernel<<<g2grid, 256>>>(st_b1, st_w2, st_b2, st_w3, 0);
    gemm2_kernel<<<g2grid, 256>>>(st_b1, st_w2, st_b2, st_w3, 1);

    loss_kernel<<<1, 256>>>(st_b3, out);
}

// round 3
// speedup vs baseline: 3.3623x; 3.3623x over previous
#include <cuda_runtime.h>
#include <cuda_bf16.h>
#include <cstdint>
#include <math.h>

// ---- problem constants ----
#define N_IMG 5
#define C_CH  256
#define HH    128
#define WWID  128
#define HW    16384
#define NP    81920            // N_IMG * HW
#define C4    1024             // 4*C
#define C2    512              // 2*C
#define THRE  0.01f

// output layout: [sparse_feature | loss | rate | sparse_mask]
#define LOSS_IDX 20971520
#define RATE_IDX 20971521
#define SM_OFF   20971522

// gaussian weights
#define G2_C 0.15915494309189535f
#define G2_E 0.09653235263005391f
#define G2_D 0.05855018091964769f
#define G1_C 0.45186276187760605f
#define G1_S 0.27406861906119697f

// ---- device scratch ----
__device__ __align__(16) float g_U[(size_t)NP * C4];
__device__ __align__(16) float g_V[(size_t)NP * C4];
__device__ __align__(16) __nv_bfloat16 g_W2hi[(size_t)C4 * C4];
__device__ __align__(16) __nv_bfloat16 g_W2lo[(size_t)C4 * C4];
__device__ __align__(16) __nv_bfloat16 g_W1hi[(size_t)C4 * C2];
__device__ __align__(16) __nv_bfloat16 g_W1lo[(size_t)C4 * C2];
__device__ float g_avg[N_IMG * C_CH];
__device__ float g_mx[N_IMG * C_CH];
__device__ float g_chatt[N_IMG * C_CH];
__device__ float g_chcoef[4 * C_CH];
__device__ float g_cmean[NP];
__device__ float g_cmax[NP];
__device__ float g_spatt[NP];
__device__ float g_act[NP];
__device__ float g_spcoef[4 * HW];
__device__ float g_tT[NP];
__device__ float g_tP[NP];
__device__ unsigned long long g_cnt;

__device__ __forceinline__ float sigmoidf(float x) { return 1.f / (1.f + expf(-x)); }
__device__ __forceinline__ float softplusf(float x) { return fmaxf(x, 0.f) + log1pf(expf(-fabsf(x))); }
__device__ __forceinline__ float g2w(int ky, int kx) {
    int d = (ky != 1) + (kx != 1);
    return d == 0 ? G2_C : (d == 1 ? G2_E : G2_D);
}

// ================= mma.sync helpers =================
__device__ __forceinline__ uint32_t smem_u32(const void* p) {
    uint32_t a;
    asm("{ .reg .u64 t; cvta.to.shared.u64 t, %1; cvt.u32.u64 %0, t; }" : "=r"(a) : "l"(p));
    return a;
}
__device__ __forceinline__ void ldsm4(uint32_t& r0, uint32_t& r1, uint32_t& r2, uint32_t& r3, uint32_t a) {
    asm volatile("ldmatrix.sync.aligned.m8n8.x4.shared.b16 {%0,%1,%2,%3}, [%4];"
                 : "=r"(r0), "=r"(r1), "=r"(r2), "=r"(r3) : "r"(a));
}
__device__ __forceinline__ void ldsm4t(uint32_t& r0, uint32_t& r1, uint32_t& r2, uint32_t& r3, uint32_t a) {
    asm volatile("ldmatrix.sync.aligned.m8n8.x4.trans.shared.b16 {%0,%1,%2,%3}, [%4];"
                 : "=r"(r0), "=r"(r1), "=r"(r2), "=r"(r3) : "r"(a));
}
__device__ __forceinline__ void mma_bf16(float* c, uint32_t a0, uint32_t a1, uint32_t a2, uint32_t a3,
                                         uint32_t b0, uint32_t b1) {
    asm volatile("mma.sync.aligned.m16n8k16.row.col.f32.bf16.bf16.f32 "
                 "{%0,%1,%2,%3}, {%4,%5,%6,%7}, {%8,%9}, {%0,%1,%2,%3};"
                 : "+f"(c[0]), "+f"(c[1]), "+f"(c[2]), "+f"(c[3])
                 : "r"(a0), "r"(a1), "r"(a2), "r"(a3), "r"(b0), "r"(b1));
}
// split (a,b) into packed bf16x2 hi and residual lo (a in low half)
__device__ __forceinline__ void split2(float a, float b, uint32_t& hi, uint32_t& lo) {
    __nv_bfloat16 ha = __float2bfloat16_rn(a);
    __nv_bfloat16 hb = __float2bfloat16_rn(b);
    __nv_bfloat16 la = __float2bfloat16_rn(a - __bfloat162float(ha));
    __nv_bfloat16 lb = __float2bfloat16_rn(b - __bfloat162float(hb));
    hi = (uint32_t)__bfloat16_as_ushort(ha) | ((uint32_t)__bfloat16_as_ushort(hb) << 16);
    lo = (uint32_t)__bfloat16_as_ushort(la) | ((uint32_t)__bfloat16_as_ushort(lb) << 16);
}

// ------------------------------------------------------------------
__global__ void init_kernel() {
    if (blockIdx.x == 0 && threadIdx.x == 0) g_cnt = 0ULL;
}

__global__ void reduce_nc_kernel(const float* __restrict__ feat) {
    int nc = blockIdx.x;
    const float* base = feat + (size_t)nc * HW;
    int t = threadIdx.x;
    float s = 0.f, m = -3.402823466e38f;
    for (int i = t; i < HW; i += 256) { float v = base[i]; s += v; m = fmaxf(m, v); }
    __shared__ float ss[256], sm[256];
    ss[t] = s; sm[t] = m;
    __syncthreads();
    for (int st = 128; st > 0; st >>= 1) {
        if (t < st) { ss[t] += ss[t + st]; sm[t] = fmaxf(sm[t], sm[t + st]); }
        __syncthreads();
    }
    if (t == 0) { g_avg[nc] = ss[0] * (1.f / HW); g_mx[nc] = sm[0]; }
}

__global__ void reduce_pix_kernel(const float* __restrict__ feat) {
    int p = blockIdx.x * blockDim.x + threadIdx.x;
    if (p >= NP) return;
    int n = p >> 14, pix = p & 16383;
    const float* base = feat + (size_t)n * C_CH * HW + pix;
    float s = 0.f, m = -3.402823466e38f;
    #pragma unroll 8
    for (int c = 0; c < C_CH; c++) { float v = base[(size_t)c * HW]; s += v; m = fmaxf(m, v); }
    g_cmean[p] = s * (1.f / C_CH);
    g_cmax[p] = m;
}

__global__ void chatt_kernel(const float* __restrict__ w1, const float* __restrict__ w2) {
    __shared__ float hs[N_IMG][16];
    int t = threadIdx.x;
    if (t < N_IMG * 16) {
        int n = t / 16, h = t % 16;
        float sa = 0.f, sm = 0.f;
        const float* wr = w1 + h * C_CH;
        const float* av = g_avg + n * C_CH;
        const float* mv = g_mx + n * C_CH;
        for (int c = 0; c < C_CH; c++) { sa += av[c] * wr[c]; sm += mv[c] * wr[c]; }
        hs[n][h] = fmaxf(sa, 0.f) + fmaxf(sm, 0.f);
    }
    __syncthreads();
    for (int idx = t; idx < N_IMG * C_CH; idx += 256) {
        int n = idx >> 8, c = idx & 255;
        float p = 0.f;
        #pragma unroll
        for (int h = 0; h < 16; h++) p += hs[n][h] * w2[c * 16 + h];
        g_chatt[idx] = sigmoidf(p);
    }
}

__global__ void spatial_kernel(const float* __restrict__ sw) {
    int idx = blockIdx.x * blockDim.x + threadIdx.x;
    if (idx >= NP) return;
    int n = idx >> 14, pix = idx & 16383;
    int h = pix >> 7, w = pix & 127;
    float satt = 0.f, act = 0.f;
    #pragma unroll
    for (int ky = 0; ky < 3; ky++) {
        int hh = h + ky - 1;
        if (hh < 0 || hh >= HH) continue;
        #pragma unroll
        for (int kx = 0; kx < 3; kx++) {
            int ww = w + kx - 1;
            if (ww < 0 || ww >= WWID) continue;
            int q = n * HW + hh * WWID + ww;
            float cm = g_cmean[q], cx = g_cmax[q];
            satt += cm * sw[ky * 3 + kx] + cx * sw[9 + ky * 3 + kx];
            act += g2w(ky, kx) * sigmoidf(cm);
        }
    }
    g_spatt[idx] = sigmoidf(satt);
    g_act[idx] = act;
}

__global__ void chcoef_kernel(const float* __restrict__ cfw) {
    __shared__ float ego[C_CH];
    __shared__ float att[4][C_CH];
    __shared__ float tmp[4][C_CH];
    int t = threadIdx.x;
    for (int i = t; i < C_CH; i += 256) ego[i] = 1.f - g_chatt[i];
    for (int i = t; i < 4 * C_CH; i += 256) att[i >> 8][i & 255] = g_chatt[C_CH + i];
    __syncthreads();
    for (int i = t; i < 4 * C_CH; i += 256) {
        int n = i >> 8, c = i & 255;
        const float* row = cfw + (size_t)c * C2;
        float p = 0.f;
        for (int k = 0; k < C_CH; k++) p += ego[k] * row[k] + att[n][k] * row[C_CH + k];
        tmp[n][c] = sigmoidf(p);
    }
    __syncthreads();
    for (int i = t; i < 4 * C_CH; i += 256) {
        int n = i >> 8, c = i & 255;
        float v = G1_C * tmp[n][c];
        if (c > 0)   v += G1_S * tmp[n][c - 1];
        if (c < 255) v += G1_S * tmp[n][c + 1];
        g_chcoef[i] = v;
    }
}

__global__ void spcoef_kernel(const float* __restrict__ spfus) {
    int idx = blockIdx.x * blockDim.x + threadIdx.x;
    if (idx >= 4 * HW) return;
    int m = idx >> 14, pix = idx & 16383;
    int h = pix >> 7, w = pix & 127;
    float wa = spfus[0], wb = spfus[1];
    float acc = 0.f;
    #pragma unroll
    for (int ky = 0; ky < 3; ky++) {
        int hh = h + ky - 1;
        if (hh < 0 || hh >= HH) continue;
        #pragma unroll
        for (int kx = 0; kx < 3; kx++) {
            int ww = w + kx - 1;
            if (ww < 0 || ww >= WWID) continue;
            int q = hh * WWID + ww;
            float pre = wa * (1.f - g_spatt[q]) + wb * g_spatt[(m + 1) * HW + q];
            acc += g2w(ky, kx) * sigmoidf(pre);
        }
    }
    g_spcoef[idx] = acc;
}

__global__ void mask_kernel(const float* __restrict__ feat,
                            float* __restrict__ out_sf, float* __restrict__ out_sm) {
    int t = threadIdx.x;
    unsigned int cnt = 0;
    const int total = N_IMG * C_CH * HW;
    for (int idx = blockIdx.x * blockDim.x + t; idx < total; idx += gridDim.x * blockDim.x) {
        int n = idx / (C_CH * HW);
        float f = feat[idx];
        float sf, sm;
        if (n == 0) { sf = f; sm = 1.f; }
        else {
            int rem = idx - n * C_CH * HW;
            int c = rem >> 14, p = rem & 16383;
            int m = n - 1;
            float v = g_chcoef[m * C_CH + c] * g_spcoef[m * HW + p] * g_act[n * HW + p];
            bool mk = v > THRE;
            sf = mk ? f : 0.f; sm = mk ? 1.f : 0.f;
            cnt += mk ? 1u : 0u;
        }
        out_sf[idx] = sf;
        out_sm[idx] = sm;
    }
    __shared__ unsigned int sc[256];
    sc[t] = cnt;
    __syncthreads();
    for (int s = 128; s > 0; s >>= 1) { if (t < s) sc[t] += sc[t + s]; __syncthreads(); }
    if (t == 0) atomicAdd(&g_cnt, (unsigned long long)sc[0]);
}

// ------------------------------------------------------------------
// weight splitters
__global__ void w2split_kernel(const float* __restrict__ W2) {
    int i = blockIdx.x * blockDim.x + threadIdx.x;
    if (i >= C4 * C4) return;
    float v = W2[i];
    __nv_bfloat16 h = __float2bfloat16_rn(v);
    g_W2hi[i] = h;
    g_W2lo[i] = __float2bfloat16_rn(v - __bfloat162float(h));
}
__global__ void w1split_kernel(const float* __restrict__ W1) {
    int i = blockIdx.x * blockDim.x + threadIdx.x;
    if (i >= C4 * C2) return;
    float v = W1[i];
    __nv_bfloat16 h = __float2bfloat16_rn(v);
    g_W1hi[i] = h;
    g_W1lo[i] = __float2bfloat16_rn(v - __bfloat162float(h));
}

// ==================================================================
// GEMM1 (mma.sync bf16 split): Out[p][j] = sum_c A[n][c][p] * W1[j][wcol+c]
// A smem: [k=32][m=128] rows of 272B (128 data bf16 + pad). B smem: [n=128][k=32] rows 80B.
#define G1_A_HI 0
#define G1_A_LO 8704
#define G1_B_HI 17408
#define G1_B_LO 27648
#define G1_STAGE 37888
__global__ __launch_bounds__(256, 1) void gemm1_mma(const float* __restrict__ feat,
                                                    const float* __restrict__ sparse) {
    extern __shared__ __align__(16) char sm1[];
    const int tid = threadIdx.x;
    const int wid = tid >> 5, lane = tid & 31;
    const int wm = wid & 3, wn = wid >> 2;
    const int g = lane >> 2, t2 = (lane & 3) * 2;
    const int jt = blockIdx.x;                 // 0..7
    const size_t P0 = (size_t)blockIdx.y * 128;
    const int which = blockIdx.z;              // 0: U from feat, 1: V from sparse
    const int n = (int)(P0 >> 14), pl = (int)(P0 & 16383);
    const float* A = (which ? sparse : feat) + (size_t)n * C_CH * HW + pl;
    const __nv_bfloat16* Bhi = g_W1hi + (size_t)jt * 128 * C2 + (which ? 256 : 0);
    const __nv_bfloat16* Blo = g_W1lo + (size_t)jt * 128 * C2 + (which ? 256 : 0);
    float* Out = which ? g_V : g_U;
    const uint32_t sb = smem_u32(sm1);

    float acc[2][8][4];
    #pragma unroll
    for (int a = 0; a < 2; a++)
        #pragma unroll
        for (int b = 0; b < 8; b++)
            #pragma unroll
            for (int c = 0; c < 4; c++) acc[a][b][c] = 0.f;

    float4 pa[4];
    uint4 pw[4];
    // prefetch chunk 0
    {
        #pragma unroll
        for (int j = 0; j < 4; j++) {
            int r = wid + 8 * j;
            pa[j] = *(const float4*)(A + (size_t)r * HW + lane * 4);
        }
        #pragma unroll
        for (int i = 0; i < 2; i++) {
            int s = tid + 256 * i;
            int o = s >> 2, q = s & 3;
            pw[i]     = *(const uint4*)(Bhi + (size_t)o * C2 + q * 8);
            pw[i + 2] = *(const uint4*)(Blo + (size_t)o * C2 + q * 8);
        }
        char* buf = sm1;
        #pragma unroll
        for (int j = 0; j < 4; j++) {
            int r = wid + 8 * j;
            uint32_t h0, l0, h1, l1;
            split2(pa[j].x, pa[j].y, h0, l0);
            split2(pa[j].z, pa[j].w, h1, l1);
            *(uint2*)(buf + G1_A_HI + r * 272 + lane * 8) = make_uint2(h0, h1);
            *(uint2*)(buf + G1_A_LO + r * 272 + lane * 8) = make_uint2(l0, l1);
        }
        #pragma unroll
        for (int i = 0; i < 2; i++) {
            int s = tid + 256 * i;
            int o = s >> 2, q = s & 3;
            *(uint4*)(buf + G1_B_HI + o * 80 + q * 16) = pw[i];
            *(uint4*)(buf + G1_B_LO + o * 80 + q * 16) = pw[i + 2];
        }
    }
    __syncthreads();

    for (int kc = 0; kc < 8; kc++) {
        if (kc + 1 < 8) {
            int k0 = (kc + 1) * 32;
            #pragma unroll
            for (int j = 0; j < 4; j++) {
                int r = wid + 8 * j;
                pa[j] = *(const float4*)(A + (size_t)(k0 + r) * HW + lane * 4);
            }
            #pragma unroll
            for (int i = 0; i < 2; i++) {
                int s = tid + 256 * i;
                int o = s >> 2, q = s & 3;
                pw[i]     = *(const uint4*)(Bhi + (size_t)o * C2 + k0 + q * 8);
                pw[i + 2] = *(const uint4*)(Blo + (size_t)o * C2 + k0 + q * 8);
            }
        }
        // compute on buf kc&1
        const uint32_t base = sb + (kc & 1) * G1_STAGE;
        #pragma unroll
        for (int ks = 0; ks < 2; ks++) {
            uint32_t bh[8][2], bl[8][2];
            #pragma unroll
            for (int np = 0; np < 4; np++) {
                int row = wn * 64 + np * 16 + (lane & 7) + ((lane >> 4) & 1) * 8;
                uint32_t col = ks * 32 + ((lane >> 3) & 1) * 16;
                uint32_t a = base + G1_B_HI + row * 80 + col;
                ldsm4(bh[2 * np][0], bh[2 * np][1], bh[2 * np + 1][0], bh[2 * np + 1][1], a);
                ldsm4(bl[2 * np][0], bl[2 * np][1], bl[2 * np + 1][0], bl[2 * np + 1][1], a + (G1_B_LO - G1_B_HI));
            }
            #pragma unroll
            for (int mf = 0; mf < 2; mf++) {
                int rowk = ks * 16 + ((lane >> 4) & 1) * 8 + (lane & 7);
                uint32_t col = (wm * 32 + mf * 16 + ((lane >> 3) & 1) * 8) * 2;
                uint32_t a = base + G1_A_HI + rowk * 272 + col;
                uint32_t ah0, ah1, ah2, ah3, al0, al1, al2, al3;
                ldsm4t(ah0, ah1, ah2, ah3, a);
                ldsm4t(al0, al1, al2, al3, a + (G1_A_LO - G1_A_HI));
                #pragma unroll
                for (int nf = 0; nf < 8; nf++) {
                    mma_bf16(acc[mf][nf], ah0, ah1, ah2, ah3, bh[nf][0], bh[nf][1]);
                    mma_bf16(acc[mf][nf], al0, al1, al2, al3, bh[nf][0], bh[nf][1]);
                    mma_bf16(acc[mf][nf], ah0, ah1, ah2, ah3, bl[nf][0], bl[nf][1]);
                }
            }
        }
        // store prefetched into other buffer
        if (kc + 1 < 8) {
            char* buf = sm1 + ((kc + 1) & 1) * G1_STAGE;
            #pragma unroll
            for (int j = 0; j < 4; j++) {
                int r = wid + 8 * j;
                uint32_t h0, l0, h1, l1;
                split2(pa[j].x, pa[j].y, h0, l0);
                split2(pa[j].z, pa[j].w, h1, l1);
                *(uint2*)(buf + G1_A_HI + r * 272 + lane * 8) = make_uint2(h0, h1);
                *(uint2*)(buf + G1_A_LO + r * 272 + lane * 8) = make_uint2(l0, l1);
            }
            #pragma unroll
            for (int i = 0; i < 2; i++) {
                int s = tid + 256 * i;
                int o = s >> 2, q = s & 3;
                *(uint4*)(buf + G1_B_HI + o * 80 + q * 16) = pw[i];
                *(uint4*)(buf + G1_B_LO + o * 80 + q * 16) = pw[i + 2];
            }
        }
        __syncthreads();
    }

    // write Out fp32 [p][j]
    #pragma unroll
    for (int mf = 0; mf < 2; mf++) {
        #pragma unroll
        for (int nf = 0; nf < 8; nf++) {
            size_t r0 = P0 + wm * 32 + mf * 16 + g;
            int col = jt * 128 + wn * 64 + nf * 8 + t2;
            *(float2*)&Out[r0 * C4 + col] = make_float2(acc[mf][nf][0], acc[mf][nf][1]);
            *(float2*)&Out[(r0 + 8) * C4 + col] = make_float2(acc[mf][nf][2], acc[mf][nf][3]);
        }
    }
}

// ==================================================================
// GEMM2 (mma.sync bf16 split, fused z-prep + epilogue):
// T[p] = sum_o relu( (z @ W2^T)[p][o] + b2[o] ) * w3[o], z = relu(U_roll + V + b1)
// A smem: [m=128][k=32] rows 80B; B smem: [o=128][k=32] rows 80B.
#define G2_A_HI 0
#define G2_A_LO 10240
#define G2_B_HI 20480
#define G2_B_LO 30720
#define G2_STAGE 40960
__global__ __launch_bounds__(256, 1) void gemm2_mma(const float* __restrict__ b1,
                                                    const float* __restrict__ b2,
                                                    const float* __restrict__ w3) {
    extern __shared__ __align__(16) char sm2[];
    const int tid = threadIdx.x;
    const int wid = tid >> 5, lane = tid & 31;
    const int wm = wid & 3, wn = wid >> 2;
    const int g = lane >> 2, t2 = (lane & 3) * 2;
    const size_t P0 = (size_t)blockIdx.x * 128;
    const int roll = blockIdx.y;
    const int n = (int)(P0 >> 14), pl = (int)(P0 & 16383);
    const int nu = roll ? ((n + 1 == N_IMG) ? 0 : n + 1) : n;
    const float* U = g_U + ((size_t)nu * HW + pl) * C4;
    const float* V = g_V + ((size_t)n * HW + pl) * C4;
    float* tOut = roll ? g_tP : g_tT;
    const uint32_t sb = smem_u32(sm2);

    float sAcc[4] = {0.f, 0.f, 0.f, 0.f};

    for (int nt = 0; nt < 8; nt++) {
        const int o0 = nt * 128;
        const __nv_bfloat16* Whi = g_W2hi + (size_t)o0 * C4;
        const __nv_bfloat16* Wlo = g_W2lo + (size_t)o0 * C4;
        float acc[2][8][4];
        #pragma unroll
        for (int a = 0; a < 2; a++)
            #pragma unroll
            for (int b = 0; b < 8; b++)
                #pragma unroll
                for (int c = 0; c < 4; c++) acc[a][b][c] = 0.f;

        float4 pu[4], pv[4];
        uint4 pw[4];
        // prefetch + store chunk 0
        {
            #pragma unroll
            for (int i = 0; i < 4; i++) {
                int s = tid + 256 * i;
                int p = s >> 3, kq = s & 7;
                pu[i] = *(const float4*)(U + (size_t)p * C4 + kq * 4);
                pv[i] = *(const float4*)(V + (size_t)p * C4 + kq * 4);
            }
            #pragma unroll
            for (int i = 0; i < 2; i++) {
                int s = tid + 256 * i;
                int o = s >> 2, q = s & 3;
                pw[i]     = *(const uint4*)(Whi + (size_t)o * C4 + q * 8);
                pw[i + 2] = *(const uint4*)(Wlo + (size_t)o * C4 + q * 8);
            }
            char* buf = sm2;
            #pragma unroll
            for (int i = 0; i < 4; i++) {
                int s = tid + 256 * i;
                int p = s >> 3, kq = s & 7;
                const float4 bb = *(const float4*)(b1 + kq * 4);
                float4 z;
                z.x = fmaxf(pu[i].x + pv[i].x + bb.x, 0.f);
                z.y = fmaxf(pu[i].y + pv[i].y + bb.y, 0.f);
                z.z = fmaxf(pu[i].z + pv[i].z + bb.z, 0.f);
                z.w = fmaxf(pu[i].w + pv[i].w + bb.w, 0.f);
                uint32_t h0, l0, h1, l1;
                split2(z.x, z.y, h0, l0);
                split2(z.z, z.w, h1, l1);
                *(uint2*)(buf + G2_A_HI + p * 80 + kq * 8) = make_uint2(h0, h1);
                *(uint2*)(buf + G2_A_LO + p * 80 + kq * 8) = make_uint2(l0, l1);
            }
            #pragma unroll
            for (int i = 0; i < 2; i++) {
                int s = tid + 256 * i;
                int o = s >> 2, q = s & 3;
                *(uint4*)(buf + G2_B_HI + o * 80 + q * 16) = pw[i];
                *(uint4*)(buf + G2_B_LO + o * 80 + q * 16) = pw[i + 2];
            }
        }
        __syncthreads();

        for (int kc = 0; kc < 32; kc++) {
            if (kc + 1 < 32) {
                int k0 = (kc + 1) * 32;
                #pragma unroll
                for (int i = 0; i < 4; i++) {
                    int s = tid + 256 * i;
                    int p = s >> 3, kq = s & 7;
                    pu[i] = *(const float4*)(U + (size_t)p * C4 + k0 + kq * 4);
                    pv[i] = *(const float4*)(V + (size_t)p * C4 + k0 + kq * 4);
                }
                #pragma unroll
                for (int i = 0; i < 2; i++) {
                    int s = tid + 256 * i;
                    int o = s >> 2, q = s & 3;
                    pw[i]     = *(const uint4*)(Whi + (size_t)o * C4 + k0 + q * 8);
                    pw[i + 2] = *(const uint4*)(Wlo + (size_t)o * C4 + k0 + q * 8);
                }
            }
            const uint32_t base = sb + (kc & 1) * G2_STAGE;
            #pragma unroll
            for (int ks = 0; ks < 2; ks++) {
                uint32_t bh[8][2], bl[8][2];
                #pragma unroll
                for (int np = 0; np < 4; np++) {
                    int row = wn * 64 + np * 16 + (lane & 7) + ((lane >> 4) & 1) * 8;
                    uint32_t col = ks * 32 + ((lane >> 3) & 1) * 16;
                    uint32_t a = base + G2_B_HI + row * 80 + col;
                    ldsm4(bh[2 * np][0], bh[2 * np][1], bh[2 * np + 1][0], bh[2 * np + 1][1], a);
                    ldsm4(bl[2 * np][0], bl[2 * np][1], bl[2 * np + 1][0], bl[2 * np + 1][1], a + (G2_B_LO - G2_B_HI));
                }
                #pragma unroll
                for (int mf = 0; mf < 2; mf++) {
                    int row = wm * 32 + mf * 16 + (lane & 7) + ((lane >> 3) & 1) * 8;
                    uint32_t col = ks * 32 + ((lane >> 4) & 1) * 16;
                    uint32_t a = base + G2_A_HI + row * 80 + col;
                    uint32_t ah0, ah1, ah2, ah3, al0, al1, al2, al3;
                    ldsm4(ah0, ah1, ah2, ah3, a);
                    ldsm4(al0, al1, al2, al3, a + (G2_A_LO - G2_A_HI));
                    #pragma unroll
                    for (int nf = 0; nf < 8; nf++) {
                        mma_bf16(acc[mf][nf], ah0, ah1, ah2, ah3, bh[nf][0], bh[nf][1]);
                        mma_bf16(acc[mf][nf], al0, al1, al2, al3, bh[nf][0], bh[nf][1]);
                        mma_bf16(acc[mf][nf], ah0, ah1, ah2, ah3, bl[nf][0], bl[nf][1]);
                    }
                }
            }
            if (kc + 1 < 32) {
                char* buf = sm2 + ((kc + 1) & 1) * G2_STAGE;
                int k0 = (kc + 1) * 32;
                #pragma unroll
                for (int i = 0; i < 4; i++) {
                    int s = tid + 256 * i;
                    int p = s >> 3, kq = s & 7;
                    const float4 bb = *(const float4*)(b1 + k0 + kq * 4);
                    float4 z;
                    z.x = fmaxf(pu[i].x + pv[i].x + bb.x, 0.f);
                    z.y = fmaxf(pu[i].y + pv[i].y + bb.y, 0.f);
                    z.z = fmaxf(pu[i].z + pv[i].z + bb.z, 0.f);
                    z.w = fmaxf(pu[i].w + pv[i].w + bb.w, 0.f);
                    uint32_t h0, l0, h1, l1;
                    split2(z.x, z.y, h0, l0);
                    split2(z.z, z.w, h1, l1);
                    *(uint2*)(buf + G2_A_HI + p * 80 + kq * 8) = make_uint2(h0, h1);
                    *(uint2*)(buf + G2_A_LO + p * 80 + kq * 8) = make_uint2(l0, l1);
                }
                #pragma unroll
                for (int i = 0; i < 2; i++) {
                    int s = tid + 256 * i;
                    int o = s >> 2, q = s & 3;
                    *(uint4*)(buf + G2_B_HI + o * 80 + q * 16) = pw[i];
                    *(uint4*)(buf + G2_B_LO + o * 80 + q * 16) = pw[i + 2];
                }
            }
            __syncthreads();
        }

        // fold this n-tile into per-pixel scalars
        #pragma unroll
        for (int mf = 0; mf < 2; mf++) {
            #pragma unroll
            for (int nf = 0; nf < 8; nf++) {
                int c0 = o0 + wn * 64 + nf * 8 + t2;
                float b2a = __ldg(b2 + c0), b2b = __ldg(b2 + c0 + 1);
                float w3a = __ldg(w3 + c0), w3b = __ldg(w3 + c0 + 1);
                sAcc[mf * 2 + 0] += fmaxf(acc[mf][nf][0] + b2a, 0.f) * w3a
                                  + fmaxf(acc[mf][nf][1] + b2b, 0.f) * w3b;
                sAcc[mf * 2 + 1] += fmaxf(acc[mf][nf][2] + b2a, 0.f) * w3a
                                  + fmaxf(acc[mf][nf][3] + b2b, 0.f) * w3b;
            }
        }
    }

    // reduce across the 4-lane groups (same rows, different cols)
    #pragma unroll
    for (int i = 0; i < 4; i++) {
        sAcc[i] += __shfl_xor_sync(0xFFFFFFFFu, sAcc[i], 1);
        sAcc[i] += __shfl_xor_sync(0xFFFFFFFFu, sAcc[i], 2);
    }
    __syncthreads();
    float* sRed = (float*)sm2;   // reuse smem: [2][128]
    if ((lane & 3) == 0) {
        #pragma unroll
        for (int i = 0; i < 4; i++) {
            int r = wm * 32 + (i >> 1) * 16 + (i & 1) * 8 + g;
            sRed[wn * 128 + r] = sAcc[i];
        }
    }
    __syncthreads();
    if (tid < 128) tOut[P0 + tid] = sRed[tid] + sRed[128 + tid];
}

// ------------------------------------------------------------------
__global__ void loss_kernel(const float* __restrict__ st_b3, float* __restrict__ out) {
    __shared__ double red[256];
    int t = threadIdx.x;
    float b3 = st_b3[0];
    double s = 0.0;
    for (int i = t; i < NP; i += 256) {
        float tt = g_tT[i] + b3;
        float tp = g_tP[i] + b3;
        s += (double)softplusf(-tt) + (double)softplusf(tp);
    }
    red[t] = s;
    __syncthreads();
    for (int st = 128; st > 0; st >>= 1) { if (t < st) red[t] += red[t + st]; __syncthreads(); }
    if (t == 0) {
        out[LOSS_IDX] = (float)(red[0] / 81920.0);
        out[RATE_IDX] = (float)((double)g_cnt / 16777216.0);
    }
}

// ------------------------------------------------------------------
extern "C" void kernel_launch(void* const* d_in, const int* in_sizes, int n_in,
                              void* d_out, int out_size) {
    const float* feat     = (const float*)d_in[0];
    const float* mlp_w1   = (const float*)d_in[1];
    const float* mlp_w2   = (const float*)d_in[2];
    const float* sp_req_w = (const float*)d_in[3];
    const float* ch_fus_w = (const float*)d_in[4];
    const float* sp_fus_w = (const float*)d_in[5];
    const float* st_w1    = (const float*)d_in[6];
    const float* st_b1    = (const float*)d_in[7];
    const float* st_w2    = (const float*)d_in[8];
    const float* st_b2    = (const float*)d_in[9];
    const float* st_w3    = (const float*)d_in[10];
    const float* st_b3    = (const float*)d_in[11];

    float* out = (float*)d_out;
    float* out_sf = out;
    float* out_sm = out + SM_OFF;

    static int attr_set = 0;
    cudaFuncSetAttribute(gemm1_mma, cudaFuncAttributeMaxDynamicSharedMemorySize, 2 * G1_STAGE);
    cudaFuncSetAttribute(gemm2_mma, cudaFuncAttributeMaxDynamicSharedMemorySize, 2 * G2_STAGE);
    (void)attr_set;

    init_kernel<<<1, 32>>>();
    reduce_nc_kernel<<<N_IMG * C_CH, 256>>>(feat);
    reduce_pix_kernel<<<(NP + 255) / 256, 256>>>(feat);
    chatt_kernel<<<1, 256>>>(mlp_w1, mlp_w2);
    spatial_kernel<<<(NP + 255) / 256, 256>>>(sp_req_w);
    chcoef_kernel<<<1, 256>>>(ch_fus_w);
    spcoef_kernel<<<(4 * HW + 255) / 256, 256>>>(sp_fus_w);
    mask_kernel<<<2048, 256>>>(feat, out_sf, out_sm);

    w1split_kernel<<<(C4 * C2 + 255) / 256, 256>>>(st_w1);
    w2split_kernel<<<(C4 * C4 + 255) / 256, 256>>>(st_w2);

    dim3 g1grid(8, NP / 128, 2);
    gemm1_mma<<<g1grid, 256, 2 * G1_STAGE>>>(feat, out_sf);

    dim3 g2grid(NP / 128, 2);
    gemm2_mma<<<g2grid, 256, 2 * G2_STAGE>>>(st_b1, st_b2, st_w3);

    loss_kernel<<<1, 256>>>(st_b3, out);
}

// round 4
// speedup vs baseline: 3.8165x; 1.1351x over previous
#include <cuda_runtime.h>
#include <cuda_bf16.h>
#include <cuda_fp16.h>
#include <cstdint>
#include <math.h>

// ---- problem constants ----
#define N_IMG 5
#define C_CH  256
#define HH    128
#define WWID  128
#define HW    16384
#define NP    81920            // N_IMG * HW
#define C4    1024             // 4*C
#define C2    512              // 2*C
#define THRE  0.01f

// output layout: [sparse_feature | loss | rate | sparse_mask]
#define LOSS_IDX 20971520
#define RATE_IDX 20971521
#define SM_OFF   20971522

// gaussian weights
#define G2_C 0.15915494309189535f
#define G2_E 0.09653235263005391f
#define G2_D 0.05855018091964769f
#define G1_C 0.45186276187760605f
#define G1_S 0.27406861906119697f

// ---- device scratch ----
__device__ __align__(16) float g_U[(size_t)NP * C4];
__device__ __align__(16) float g_V[(size_t)NP * C4];
__device__ __align__(16) __half g_W2h[(size_t)C4 * C4];
__device__ __align__(16) __half g_W1h[(size_t)C4 * C2];
__device__ float g_avg[N_IMG * C_CH];
__device__ float g_mx[N_IMG * C_CH];
__device__ float g_chatt[N_IMG * C_CH];
__device__ float g_chcoef[4 * C_CH];
__device__ float g_cmean[NP];
__device__ float g_cmax[NP];
__device__ float g_spatt[NP];
__device__ float g_act[NP];
__device__ float g_spcoef[4 * HW];
__device__ float g_tT[NP];
__device__ float g_tP[NP];
__device__ unsigned long long g_cnt;

__device__ __forceinline__ float sigmoidf(float x) { return 1.f / (1.f + expf(-x)); }
__device__ __forceinline__ float softplusf(float x) { return fmaxf(x, 0.f) + log1pf(expf(-fabsf(x))); }
__device__ __forceinline__ float g2w(int ky, int kx) {
    int d = (ky != 1) + (kx != 1);
    return d == 0 ? G2_C : (d == 1 ? G2_E : G2_D);
}

// ================= mma.sync helpers =================
__device__ __forceinline__ uint32_t smem_u32(const void* p) {
    uint32_t a;
    asm("{ .reg .u64 t; cvta.to.shared.u64 t, %1; cvt.u32.u64 %0, t; }" : "=r"(a) : "l"(p));
    return a;
}
__device__ __forceinline__ void ldsm4(uint32_t& r0, uint32_t& r1, uint32_t& r2, uint32_t& r3, uint32_t a) {
    asm volatile("ldmatrix.sync.aligned.m8n8.x4.shared.b16 {%0,%1,%2,%3}, [%4];"
                 : "=r"(r0), "=r"(r1), "=r"(r2), "=r"(r3) : "r"(a));
}
__device__ __forceinline__ void ldsm4t(uint32_t& r0, uint32_t& r1, uint32_t& r2, uint32_t& r3, uint32_t a) {
    asm volatile("ldmatrix.sync.aligned.m8n8.x4.trans.shared.b16 {%0,%1,%2,%3}, [%4];"
                 : "=r"(r0), "=r"(r1), "=r"(r2), "=r"(r3) : "r"(a));
}
__device__ __forceinline__ void mma_f16(float* c, uint32_t a0, uint32_t a1, uint32_t a2, uint32_t a3,
                                        uint32_t b0, uint32_t b1) {
    asm volatile("mma.sync.aligned.m16n8k16.row.col.f32.f16.f16.f32 "
                 "{%0,%1,%2,%3}, {%4,%5,%6,%7}, {%8,%9}, {%0,%1,%2,%3};"
                 : "+f"(c[0]), "+f"(c[1]), "+f"(c[2]), "+f"(c[3])
                 : "r"(a0), "r"(a1), "r"(a2), "r"(a3), "r"(b0), "r"(b1));
}
// split (a,b) into packed fp16x2 hi and residual lo (a in low half)
__device__ __forceinline__ void split2h(float a, float b, uint32_t& hi, uint32_t& lo) {
    __half ha = __float2half_rn(a);
    __half hb = __float2half_rn(b);
    __half la = __float2half_rn(a - __half2float(ha));
    __half lb = __float2half_rn(b - __half2float(hb));
    hi = (uint32_t)__half_as_ushort(ha) | ((uint32_t)__half_as_ushort(hb) << 16);
    lo = (uint32_t)__half_as_ushort(la) | ((uint32_t)__half_as_ushort(lb) << 16);
}

// ------------------------------------------------------------------
__global__ void init_kernel() {
    if (blockIdx.x == 0 && threadIdx.x == 0) g_cnt = 0ULL;
}

__global__ void reduce_nc_kernel(const float* __restrict__ feat) {
    int nc = blockIdx.x;
    const float* base = feat + (size_t)nc * HW;
    int t = threadIdx.x;
    float s = 0.f, m = -3.402823466e38f;
    for (int i = t; i < HW; i += 256) { float v = base[i]; s += v; m = fmaxf(m, v); }
    __shared__ float ss[256], sm[256];
    ss[t] = s; sm[t] = m;
    __syncthreads();
    for (int st = 128; st > 0; st >>= 1) {
        if (t < st) { ss[t] += ss[t + st]; sm[t] = fmaxf(sm[t], sm[t + st]); }
        __syncthreads();
    }
    if (t == 0) { g_avg[nc] = ss[0] * (1.f / HW); g_mx[nc] = sm[0]; }
}

__global__ void reduce_pix_kernel(const float* __restrict__ feat) {
    int p = blockIdx.x * blockDim.x + threadIdx.x;
    if (p >= NP) return;
    int n = p >> 14, pix = p & 16383;
    const float* base = feat + (size_t)n * C_CH * HW + pix;
    float s = 0.f, m = -3.402823466e38f;
    #pragma unroll 8
    for (int c = 0; c < C_CH; c++) { float v = base[(size_t)c * HW]; s += v; m = fmaxf(m, v); }
    g_cmean[p] = s * (1.f / C_CH);
    g_cmax[p] = m;
}

__global__ void chatt_kernel(const float* __restrict__ w1, const float* __restrict__ w2) {
    __shared__ float hs[N_IMG][16];
    int t = threadIdx.x;
    if (t < N_IMG * 16) {
        int n = t / 16, h = t % 16;
        float sa = 0.f, sm = 0.f;
        const float* wr = w1 + h * C_CH;
        const float* av = g_avg + n * C_CH;
        const float* mv = g_mx + n * C_CH;
        for (int c = 0; c < C_CH; c++) { sa += av[c] * wr[c]; sm += mv[c] * wr[c]; }
        hs[n][h] = fmaxf(sa, 0.f) + fmaxf(sm, 0.f);
    }
    __syncthreads();
    for (int idx = t; idx < N_IMG * C_CH; idx += 256) {
        int n = idx >> 8, c = idx & 255;
        float p = 0.f;
        #pragma unroll
        for (int h = 0; h < 16; h++) p += hs[n][h] * w2[c * 16 + h];
        g_chatt[idx] = sigmoidf(p);
    }
}

__global__ void spatial_kernel(const float* __restrict__ sw) {
    int idx = blockIdx.x * blockDim.x + threadIdx.x;
    if (idx >= NP) return;
    int n = idx >> 14, pix = idx & 16383;
    int h = pix >> 7, w = pix & 127;
    float satt = 0.f, act = 0.f;
    #pragma unroll
    for (int ky = 0; ky < 3; ky++) {
        int hh = h + ky - 1;
        if (hh < 0 || hh >= HH) continue;
        #pragma unroll
        for (int kx = 0; kx < 3; kx++) {
            int ww = w + kx - 1;
            if (ww < 0 || ww >= WWID) continue;
            int q = n * HW + hh * WWID + ww;
            float cm = g_cmean[q], cx = g_cmax[q];
            satt += cm * sw[ky * 3 + kx] + cx * sw[9 + ky * 3 + kx];
            act += g2w(ky, kx) * sigmoidf(cm);
        }
    }
    g_spatt[idx] = sigmoidf(satt);
    g_act[idx] = act;
}

__global__ void chcoef_kernel(const float* __restrict__ cfw) {
    __shared__ float ego[C_CH];
    __shared__ float att[4][C_CH];
    __shared__ float tmp[4][C_CH];
    int t = threadIdx.x;
    for (int i = t; i < C_CH; i += 256) ego[i] = 1.f - g_chatt[i];
    for (int i = t; i < 4 * C_CH; i += 256) att[i >> 8][i & 255] = g_chatt[C_CH + i];
    __syncthreads();
    for (int i = t; i < 4 * C_CH; i += 256) {
        int n = i >> 8, c = i & 255;
        const float* row = cfw + (size_t)c * C2;
        float p = 0.f;
        for (int k = 0; k < C_CH; k++) p += ego[k] * row[k] + att[n][k] * row[C_CH + k];
        tmp[n][c] = sigmoidf(p);
    }
    __syncthreads();
    for (int i = t; i < 4 * C_CH; i += 256) {
        int n = i >> 8, c = i & 255;
        float v = G1_C * tmp[n][c];
        if (c > 0)   v += G1_S * tmp[n][c - 1];
        if (c < 255) v += G1_S * tmp[n][c + 1];
        g_chcoef[i] = v;
    }
}

__global__ void spcoef_kernel(const float* __restrict__ spfus) {
    int idx = blockIdx.x * blockDim.x + threadIdx.x;
    if (idx >= 4 * HW) return;
    int m = idx >> 14, pix = idx & 16383;
    int h = pix >> 7, w = pix & 127;
    float wa = spfus[0], wb = spfus[1];
    float acc = 0.f;
    #pragma unroll
    for (int ky = 0; ky < 3; ky++) {
        int hh = h + ky - 1;
        if (hh < 0 || hh >= HH) continue;
        #pragma unroll
        for (int kx = 0; kx < 3; kx++) {
            int ww = w + kx - 1;
            if (ww < 0 || ww >= WWID) continue;
            int q = hh * WWID + ww;
            float pre = wa * (1.f - g_spatt[q]) + wb * g_spatt[(m + 1) * HW + q];
            acc += g2w(ky, kx) * sigmoidf(pre);
        }
    }
    g_spcoef[idx] = acc;
}

__global__ void mask_kernel(const float* __restrict__ feat,
                            float* __restrict__ out_sf, float* __restrict__ out_sm) {
    int t = threadIdx.x;
    unsigned int cnt = 0;
    const int total = N_IMG * C_CH * HW;
    for (int idx = blockIdx.x * blockDim.x + t; idx < total; idx += gridDim.x * blockDim.x) {
        int n = idx / (C_CH * HW);
        float f = feat[idx];
        float sf, sm;
        if (n == 0) { sf = f; sm = 1.f; }
        else {
            int rem = idx - n * C_CH * HW;
            int c = rem >> 14, p = rem & 16383;
            int m = n - 1;
            float v = g_chcoef[m * C_CH + c] * g_spcoef[m * HW + p] * g_act[n * HW + p];
            bool mk = v > THRE;
            sf = mk ? f : 0.f; sm = mk ? 1.f : 0.f;
            cnt += mk ? 1u : 0u;
        }
        out_sf[idx] = sf;
        out_sm[idx] = sm;
    }
    __shared__ unsigned int sc[256];
    sc[t] = cnt;
    __syncthreads();
    for (int s = 128; s > 0; s >>= 1) { if (t < s) sc[t] += sc[t + s]; __syncthreads(); }
    if (t == 0) atomicAdd(&g_cnt, (unsigned long long)sc[0]);
}

// ------------------------------------------------------------------
// weight converters (fp16)
__global__ void w2h_kernel(const float* __restrict__ W2) {
    int i = blockIdx.x * blockDim.x + threadIdx.x;
    if (i < C4 * C4) g_W2h[i] = __float2half_rn(W2[i]);
}
__global__ void w1h_kernel(const float* __restrict__ W1) {
    int i = blockIdx.x * blockDim.x + threadIdx.x;
    if (i < C4 * C2) g_W1h[i] = __float2half_rn(W1[i]);
}

// ==================================================================
// GEMM1 (mma.sync fp16, A split 2-term): Out[p][j] = sum_c A[n][c][p] * W1[j][wcol+c]
// A smem: [k=32][m=128] rows of 272B. B smem: [n=128][k=32] rows 80B.
#define G1_A_HI 0
#define G1_A_LO 8704
#define G1_B_HI 17408
#define G1_STAGE 27648
__global__ __launch_bounds__(256, 1) void gemm1_mma(const float* __restrict__ feat,
                                                    const float* __restrict__ sparse) {
    extern __shared__ __align__(16) char sm1[];
    const int tid = threadIdx.x;
    const int wid = tid >> 5, lane = tid & 31;
    const int wm = wid & 3, wn = wid >> 2;
    const int g = lane >> 2, t2 = (lane & 3) * 2;
    const int jt = blockIdx.x;                 // 0..7
    const size_t P0 = (size_t)blockIdx.y * 128;
    const int which = blockIdx.z;              // 0: U from feat, 1: V from sparse
    const int n = (int)(P0 >> 14), pl = (int)(P0 & 16383);
    const float* A = (which ? sparse : feat) + (size_t)n * C_CH * HW + pl;
    const __half* Bh = g_W1h + (size_t)jt * 128 * C2 + (which ? 256 : 0);
    float* Out = which ? g_V : g_U;
    const uint32_t sb = smem_u32(sm1);

    float acc[2][8][4];
    #pragma unroll
    for (int a = 0; a < 2; a++)
        #pragma unroll
        for (int b = 0; b < 8; b++)
            #pragma unroll
            for (int c = 0; c < 4; c++) acc[a][b][c] = 0.f;

    float4 pa[4];
    uint4 pw[2];
    // prefetch + store chunk 0
    {
        #pragma unroll
        for (int j = 0; j < 4; j++) {
            int r = wid + 8 * j;
            pa[j] = *(const float4*)(A + (size_t)r * HW + lane * 4);
        }
        #pragma unroll
        for (int i = 0; i < 2; i++) {
            int s = tid + 256 * i;
            int o = s >> 2, q = s & 3;
            pw[i] = *(const uint4*)(Bh + (size_t)o * C2 + q * 8);
        }
        char* buf = sm1;
        #pragma unroll
        for (int j = 0; j < 4; j++) {
            int r = wid + 8 * j;
            uint32_t h0, l0, h1, l1;
            split2h(pa[j].x, pa[j].y, h0, l0);
            split2h(pa[j].z, pa[j].w, h1, l1);
            *(uint2*)(buf + G1_A_HI + r * 272 + lane * 8) = make_uint2(h0, h1);
            *(uint2*)(buf + G1_A_LO + r * 272 + lane * 8) = make_uint2(l0, l1);
        }
        #pragma unroll
        for (int i = 0; i < 2; i++) {
            int s = tid + 256 * i;
            int o = s >> 2, q = s & 3;
            *(uint4*)(buf + G1_B_HI + o * 80 + q * 16) = pw[i];
        }
    }
    __syncthreads();

    for (int kc = 0; kc < 8; kc++) {
        if (kc + 1 < 8) {
            int k0 = (kc + 1) * 32;
            #pragma unroll
            for (int j = 0; j < 4; j++) {
                int r = wid + 8 * j;
                pa[j] = *(const float4*)(A + (size_t)(k0 + r) * HW + lane * 4);
            }
            #pragma unroll
            for (int i = 0; i < 2; i++) {
                int s = tid + 256 * i;
                int o = s >> 2, q = s & 3;
                pw[i] = *(const uint4*)(Bh + (size_t)o * C2 + k0 + q * 8);
            }
        }
        const uint32_t base = sb + (kc & 1) * G1_STAGE;
        #pragma unroll
        for (int ks = 0; ks < 2; ks++) {
            uint32_t bh[8][2];
            #pragma unroll
            for (int np = 0; np < 4; np++) {
                int row = wn * 64 + np * 16 + (lane & 7) + ((lane >> 4) & 1) * 8;
                uint32_t col = ks * 32 + ((lane >> 3) & 1) * 16;
                uint32_t a = base + G1_B_HI + row * 80 + col;
                ldsm4(bh[2 * np][0], bh[2 * np][1], bh[2 * np + 1][0], bh[2 * np + 1][1], a);
            }
            #pragma unroll
            for (int mf = 0; mf < 2; mf++) {
                int rowk = ks * 16 + ((lane >> 4) & 1) * 8 + (lane & 7);
                uint32_t col = (wm * 32 + mf * 16 + ((lane >> 3) & 1) * 8) * 2;
                uint32_t a = base + G1_A_HI + rowk * 272 + col;
                uint32_t ah0, ah1, ah2, ah3, al0, al1, al2, al3;
                ldsm4t(ah0, ah1, ah2, ah3, a);
                ldsm4t(al0, al1, al2, al3, a + (G1_A_LO - G1_A_HI));
                #pragma unroll
                for (int nf = 0; nf < 8; nf++) {
                    mma_f16(acc[mf][nf], ah0, ah1, ah2, ah3, bh[nf][0], bh[nf][1]);
                    mma_f16(acc[mf][nf], al0, al1, al2, al3, bh[nf][0], bh[nf][1]);
                }
            }
        }
        if (kc + 1 < 8) {
            char* buf = sm1 + ((kc + 1) & 1) * G1_STAGE;
            #pragma unroll
            for (int j = 0; j < 4; j++) {
                int r = wid + 8 * j;
                uint32_t h0, l0, h1, l1;
                split2h(pa[j].x, pa[j].y, h0, l0);
                split2h(pa[j].z, pa[j].w, h1, l1);
                *(uint2*)(buf + G1_A_HI + r * 272 + lane * 8) = make_uint2(h0, h1);
                *(uint2*)(buf + G1_A_LO + r * 272 + lane * 8) = make_uint2(l0, l1);
            }
            #pragma unroll
            for (int i = 0; i < 2; i++) {
                int s = tid + 256 * i;
                int o = s >> 2, q = s & 3;
                *(uint4*)(buf + G1_B_HI + o * 80 + q * 16) = pw[i];
            }
        }
        __syncthreads();
    }

    // write Out fp32 [p][j]
    #pragma unroll
    for (int mf = 0; mf < 2; mf++) {
        #pragma unroll
        for (int nf = 0; nf < 8; nf++) {
            size_t r0 = P0 + wm * 32 + mf * 16 + g;
            int col = jt * 128 + wn * 64 + nf * 8 + t2;
            *(float2*)&Out[r0 * C4 + col] = make_float2(acc[mf][nf][0], acc[mf][nf][1]);
            *(float2*)&Out[(r0 + 8) * C4 + col] = make_float2(acc[mf][nf][2], acc[mf][nf][3]);
        }
    }
}

// ==================================================================
// GEMM2 (mma.sync fp16, A split 2-term, fused z-prep + epilogue):
// T[p] = sum_o relu( (z @ W2^T)[p][o] + b2[o] ) * w3[o], z = relu(U_roll + V + b1)
// A smem: [m=128][k=32] rows 80B; B smem: [o=128][k=32] rows 80B.
#define G2_A_HI 0
#define G2_A_LO 10240
#define G2_B_HI 20480
#define G2_STAGE 30720
__global__ __launch_bounds__(256, 1) void gemm2_mma(const float* __restrict__ b1,
                                                    const float* __restrict__ b2,
                                                    const float* __restrict__ w3) {
    extern __shared__ __align__(16) char sm2[];
    const int tid = threadIdx.x;
    const int wid = tid >> 5, lane = tid & 31;
    const int wm = wid & 3, wn = wid >> 2;
    const int g = lane >> 2, t2 = (lane & 3) * 2;
    const size_t P0 = (size_t)blockIdx.x * 128;
    const int roll = blockIdx.y;
    const int n = (int)(P0 >> 14), pl = (int)(P0 & 16383);
    const int nu = roll ? ((n + 1 == N_IMG) ? 0 : n + 1) : n;
    const float* U = g_U + ((size_t)nu * HW + pl) * C4;
    const float* V = g_V + ((size_t)n * HW + pl) * C4;
    float* tOut = roll ? g_tP : g_tT;
    const uint32_t sb = smem_u32(sm2);

    float sAcc[4] = {0.f, 0.f, 0.f, 0.f};

    for (int nt = 0; nt < 8; nt++) {
        const int o0 = nt * 128;
        const __half* Wh = g_W2h + (size_t)o0 * C4;
        float acc[2][8][4];
        #pragma unroll
        for (int a = 0; a < 2; a++)
            #pragma unroll
            for (int b = 0; b < 8; b++)
                #pragma unroll
                for (int c = 0; c < 4; c++) acc[a][b][c] = 0.f;

        float4 pu[4], pv[4];
        uint4 pw[2];
        // prefetch + store chunk 0
        {
            #pragma unroll
            for (int i = 0; i < 4; i++) {
                int s = tid + 256 * i;
                int p = s >> 3, kq = s & 7;
                pu[i] = *(const float4*)(U + (size_t)p * C4 + kq * 4);
                pv[i] = *(const float4*)(V + (size_t)p * C4 + kq * 4);
            }
            #pragma unroll
            for (int i = 0; i < 2; i++) {
                int s = tid + 256 * i;
                int o = s >> 2, q = s & 3;
                pw[i] = *(const uint4*)(Wh + (size_t)o * C4 + q * 8);
            }
            char* buf = sm2;
            #pragma unroll
            for (int i = 0; i < 4; i++) {
                int s = tid + 256 * i;
                int p = s >> 3, kq = s & 7;
                const float4 bb = *(const float4*)(b1 + kq * 4);
                float4 z;
                z.x = fmaxf(pu[i].x + pv[i].x + bb.x, 0.f);
                z.y = fmaxf(pu[i].y + pv[i].y + bb.y, 0.f);
                z.z = fmaxf(pu[i].z + pv[i].z + bb.z, 0.f);
                z.w = fmaxf(pu[i].w + pv[i].w + bb.w, 0.f);
                uint32_t h0, l0, h1, l1;
                split2h(z.x, z.y, h0, l0);
                split2h(z.z, z.w, h1, l1);
                *(uint2*)(buf + G2_A_HI + p * 80 + kq * 8) = make_uint2(h0, h1);
                *(uint2*)(buf + G2_A_LO + p * 80 + kq * 8) = make_uint2(l0, l1);
            }
            #pragma unroll
            for (int i = 0; i < 2; i++) {
                int s = tid + 256 * i;
                int o = s >> 2, q = s & 3;
                *(uint4*)(buf + G2_B_HI + o * 80 + q * 16) = pw[i];
            }
        }
        __syncthreads();

        for (int kc = 0; kc < 32; kc++) {
            if (kc + 1 < 32) {
                int k0 = (kc + 1) * 32;
                #pragma unroll
                for (int i = 0; i < 4; i++) {
                    int s = tid + 256 * i;
                    int p = s >> 3, kq = s & 7;
                    pu[i] = *(const float4*)(U + (size_t)p * C4 + k0 + kq * 4);
                    pv[i] = *(const float4*)(V + (size_t)p * C4 + k0 + kq * 4);
                }
                #pragma unroll
                for (int i = 0; i < 2; i++) {
                    int s = tid + 256 * i;
                    int o = s >> 2, q = s & 3;
                    pw[i] = *(const uint4*)(Wh + (size_t)o * C4 + k0 + q * 8);
                }
            }
            const uint32_t base = sb + (kc & 1) * G2_STAGE;
            #pragma unroll
            for (int ks = 0; ks < 2; ks++) {
                uint32_t bh[8][2];
                #pragma unroll
                for (int np = 0; np < 4; np++) {
                    int row = wn * 64 + np * 16 + (lane & 7) + ((lane >> 4) & 1) * 8;
                    uint32_t col = ks * 32 + ((lane >> 3) & 1) * 16;
                    uint32_t a = base + G2_B_HI + row * 80 + col;
                    ldsm4(bh[2 * np][0], bh[2 * np][1], bh[2 * np + 1][0], bh[2 * np + 1][1], a);
                }
                #pragma unroll
                for (int mf = 0; mf < 2; mf++) {
                    int row = wm * 32 + mf * 16 + (lane & 7) + ((lane >> 3) & 1) * 8;
                    uint32_t col = ks * 32 + ((lane >> 4) & 1) * 16;
                    uint32_t a = base + G2_A_HI + row * 80 + col;
                    uint32_t ah0, ah1, ah2, ah3, al0, al1, al2, al3;
                    ldsm4(ah0, ah1, ah2, ah3, a);
                    ldsm4(al0, al1, al2, al3, a + (G2_A_LO - G2_A_HI));
                    #pragma unroll
                    for (int nf = 0; nf < 8; nf++) {
                        mma_f16(acc[mf][nf], ah0, ah1, ah2, ah3, bh[nf][0], bh[nf][1]);
                        mma_f16(acc[mf][nf], al0, al1, al2, al3, bh[nf][0], bh[nf][1]);
                    }
                }
            }
            if (kc + 1 < 32) {
                char* buf = sm2 + ((kc + 1) & 1) * G2_STAGE;
                int k0 = (kc + 1) * 32;
                #pragma unroll
                for (int i = 0; i < 4; i++) {
                    int s = tid + 256 * i;
                    int p = s >> 3, kq = s & 7;
                    const float4 bb = *(const float4*)(b1 + k0 + kq * 4);
                    float4 z;
                    z.x = fmaxf(pu[i].x + pv[i].x + bb.x, 0.f);
                    z.y = fmaxf(pu[i].y + pv[i].y + bb.y, 0.f);
                    z.z = fmaxf(pu[i].z + pv[i].z + bb.z, 0.f);
                    z.w = fmaxf(pu[i].w + pv[i].w + bb.w, 0.f);
                    uint32_t h0, l0, h1, l1;
                    split2h(z.x, z.y, h0, l0);
                    split2h(z.z, z.w, h1, l1);
                    *(uint2*)(buf + G2_A_HI + p * 80 + kq * 8) = make_uint2(h0, h1);
                    *(uint2*)(buf + G2_A_LO + p * 80 + kq * 8) = make_uint2(l0, l1);
                }
                #pragma unroll
                for (int i = 0; i < 2; i++) {
                    int s = tid + 256 * i;
                    int o = s >> 2, q = s & 3;
                    *(uint4*)(buf + G2_B_HI + o * 80 + q * 16) = pw[i];
                }
            }
            __syncthreads();
        }

        // fold this n-tile into per-pixel scalars
        #pragma unroll
        for (int mf = 0; mf < 2; mf++) {
            #pragma unroll
            for (int nf = 0; nf < 8; nf++) {
                int c0 = o0 + wn * 64 + nf * 8 + t2;
                float b2a = __ldg(b2 + c0), b2b = __ldg(b2 + c0 + 1);
                float w3a = __ldg(w3 + c0), w3b = __ldg(w3 + c0 + 1);
                sAcc[mf * 2 + 0] += fmaxf(acc[mf][nf][0] + b2a, 0.f) * w3a
                                  + fmaxf(acc[mf][nf][1] + b2b, 0.f) * w3b;
                sAcc[mf * 2 + 1] += fmaxf(acc[mf][nf][2] + b2a, 0.f) * w3a
                                  + fmaxf(acc[mf][nf][3] + b2b, 0.f) * w3b;
            }
        }
    }

    // reduce across the 4-lane groups (same rows, different cols)
    #pragma unroll
    for (int i = 0; i < 4; i++) {
        sAcc[i] += __shfl_xor_sync(0xFFFFFFFFu, sAcc[i], 1);
        sAcc[i] += __shfl_xor_sync(0xFFFFFFFFu, sAcc[i], 2);
    }
    __syncthreads();
    float* sRed = (float*)sm2;   // reuse smem: [2][128]
    if ((lane & 3) == 0) {
        #pragma unroll
        for (int i = 0; i < 4; i++) {
            int r = wm * 32 + (i >> 1) * 16 + (i & 1) * 8 + g;
            sRed[wn * 128 + r] = sAcc[i];
        }
    }
    __syncthreads();
    if (tid < 128) tOut[P0 + tid] = sRed[tid] + sRed[128 + tid];
}

// ------------------------------------------------------------------
__global__ void loss_kernel(const float* __restrict__ st_b3, float* __restrict__ out) {
    __shared__ double red[256];
    int t = threadIdx.x;
    float b3 = st_b3[0];
    double s = 0.0;
    for (int i = t; i < NP; i += 256) {
        float tt = g_tT[i] + b3;
        float tp = g_tP[i] + b3;
        s += (double)softplusf(-tt) + (double)softplusf(tp);
    }
    red[t] = s;
    __syncthreads();
    for (int st = 128; st > 0; st >>= 1) { if (t < st) red[t] += red[t + st]; __syncthreads(); }
    if (t == 0) {
        out[LOSS_IDX] = (float)(red[0] / 81920.0);
        out[RATE_IDX] = (float)((double)g_cnt / 16777216.0);
    }
}

// ------------------------------------------------------------------
extern "C" void kernel_launch(void* const* d_in, const int* in_sizes, int n_in,
                              void* d_out, int out_size) {
    const float* feat     = (const float*)d_in[0];
    const float* mlp_w1   = (const float*)d_in[1];
    const float* mlp_w2   = (const float*)d_in[2];
    const float* sp_req_w = (const float*)d_in[3];
    const float* ch_fus_w = (const float*)d_in[4];
    const float* sp_fus_w = (const float*)d_in[5];
    const float* st_w1    = (const float*)d_in[6];
    const float* st_b1    = (const float*)d_in[7];
    const float* st_w2    = (const float*)d_in[8];
    const float* st_b2    = (const float*)d_in[9];
    const float* st_w3    = (const float*)d_in[10];
    const float* st_b3    = (const float*)d_in[11];

    float* out = (float*)d_out;
    float* out_sf = out;
    float* out_sm = out + SM_OFF;

    cudaFuncSetAttribute(gemm1_mma, cudaFuncAttributeMaxDynamicSharedMemorySize, 2 * G1_STAGE);
    cudaFuncSetAttribute(gemm2_mma, cudaFuncAttributeMaxDynamicSharedMemorySize, 2 * G2_STAGE);

    init_kernel<<<1, 32>>>();
    reduce_nc_kernel<<<N_IMG * C_CH, 256>>>(feat);
    reduce_pix_kernel<<<(NP + 255) / 256, 256>>>(feat);
    chatt_kernel<<<1, 256>>>(mlp_w1, mlp_w2);
    spatial_kernel<<<(NP + 255) / 256, 256>>>(sp_req_w);
    chcoef_kernel<<<1, 256>>>(ch_fus_w);
    spcoef_kernel<<<(4 * HW + 255) / 256, 256>>>(sp_fus_w);
    mask_kernel<<<2048, 256>>>(feat, out_sf, out_sm);

    w1h_kernel<<<(C4 * C2 + 255) / 256, 256>>>(st_w1);
    w2h_kernel<<<(C4 * C4 + 255) / 256, 256>>>(st_w2);

    dim3 g1grid(8, NP / 128, 2);
    gemm1_mma<<<g1grid, 256, 2 * G1_STAGE>>>(feat, out_sf);

    dim3 g2grid(NP / 128, 2);
    gemm2_mma<<<g2grid, 256, 2 * G2_STAGE>>>(st_b1, st_b2, st_w3);

    loss_kernel<<<1, 256>>>(st_b3, out);
}

// round 5
// speedup vs baseline: 4.3972x; 1.1521x over previous
#include <cuda_runtime.h>
#include <cuda_bf16.h>
#include <cuda_fp16.h>
#include <cstdint>
#include <math.h>

// ---- problem constants ----
#define N_IMG 5
#define C_CH  256
#define HH    128
#define WWID  128
#define HW    16384
#define NP    81920            // N_IMG * HW
#define C4    1024             // 4*C
#define C2    512              // 2*C
#define THRE  0.01f
#define NCHW_TOT (N_IMG * C_CH * HW)

// output layout: [sparse_feature | loss | rate | sparse_mask]
#define LOSS_IDX 20971520
#define RATE_IDX 20971521
#define SM_OFF   20971522

// gaussian weights
#define G2_C 0.15915494309189535f
#define G2_E 0.09653235263005391f
#define G2_D 0.05855018091964769f
#define G1_C 0.45186276187760605f
#define G1_S 0.27406861906119697f

// ---- device scratch ----
__device__ __align__(16) float g_U[(size_t)NP * C4];
__device__ __align__(16) float g_V[(size_t)NP * C4];
__device__ __align__(16) __half g_ZThi[(size_t)NP * C4];
__device__ __align__(16) __half g_ZTlo[(size_t)NP * C4];
__device__ __align__(16) __half g_ZPhi[(size_t)NP * C4];
__device__ __align__(16) __half g_ZPlo[(size_t)NP * C4];
__device__ __align__(16) __half g_Fhi[(size_t)NCHW_TOT];
__device__ __align__(16) __half g_Flo[(size_t)NCHW_TOT];
__device__ __align__(16) __half g_Shi[(size_t)NCHW_TOT];
__device__ __align__(16) __half g_Slo[(size_t)NCHW_TOT];
__device__ __align__(16) __half g_W2h[(size_t)C4 * C4];
__device__ __align__(16) __half g_W1h[(size_t)C4 * C2];
__device__ float g_avg[N_IMG * C_CH];
__device__ float g_mx[N_IMG * C_CH];
__device__ float g_chatt[N_IMG * C_CH];
__device__ float g_chcoef[4 * C_CH];
__device__ float g_cmean[NP];
__device__ float g_cmax[NP];
__device__ float g_spatt[NP];
__device__ float g_act[NP];
__device__ float g_spcoef[4 * HW];
__device__ float g_tT[NP];
__device__ float g_tP[NP];
__device__ unsigned long long g_cnt;

__device__ __forceinline__ float sigmoidf(float x) { return 1.f / (1.f + expf(-x)); }
__device__ __forceinline__ float softplusf(float x) { return fmaxf(x, 0.f) + log1pf(expf(-fabsf(x))); }
__device__ __forceinline__ float g2w(int ky, int kx) {
    int d = (ky != 1) + (kx != 1);
    return d == 0 ? G2_C : (d == 1 ? G2_E : G2_D);
}

// ================= mma.sync helpers =================
__device__ __forceinline__ uint32_t smem_u32(const void* p) {
    uint32_t a;
    asm("{ .reg .u64 t; cvta.to.shared.u64 t, %1; cvt.u32.u64 %0, t; }" : "=r"(a) : "l"(p));
    return a;
}
__device__ __forceinline__ void ldsm4(uint32_t& r0, uint32_t& r1, uint32_t& r2, uint32_t& r3, uint32_t a) {
    asm volatile("ldmatrix.sync.aligned.m8n8.x4.shared.b16 {%0,%1,%2,%3}, [%4];"
                 : "=r"(r0), "=r"(r1), "=r"(r2), "=r"(r3) : "r"(a));
}
__device__ __forceinline__ void ldsm4t(uint32_t& r0, uint32_t& r1, uint32_t& r2, uint32_t& r3, uint32_t a) {
    asm volatile("ldmatrix.sync.aligned.m8n8.x4.trans.shared.b16 {%0,%1,%2,%3}, [%4];"
                 : "=r"(r0), "=r"(r1), "=r"(r2), "=r"(r3) : "r"(a));
}
__device__ __forceinline__ void mma_f16(float* c, uint32_t a0, uint32_t a1, uint32_t a2, uint32_t a3,
                                        uint32_t b0, uint32_t b1) {
    asm volatile("mma.sync.aligned.m16n8k16.row.col.f32.f16.f16.f32 "
                 "{%0,%1,%2,%3}, {%4,%5,%6,%7}, {%8,%9}, {%0,%1,%2,%3};"
                 : "+f"(c[0]), "+f"(c[1]), "+f"(c[2]), "+f"(c[3])
                 : "r"(a0), "r"(a1), "r"(a2), "r"(a3), "r"(b0), "r"(b1));
}
// split (a,b) into packed fp16x2 hi and residual lo (a in low half)
__device__ __forceinline__ void split2h(float a, float b, uint32_t& hi, uint32_t& lo) {
    __half ha = __float2half_rn(a);
    __half hb = __float2half_rn(b);
    __half la = __float2half_rn(a - __half2float(ha));
    __half lb = __float2half_rn(b - __half2float(hb));
    hi = (uint32_t)__half_as_ushort(ha) | ((uint32_t)__half_as_ushort(hb) << 16);
    lo = (uint32_t)__half_as_ushort(la) | ((uint32_t)__half_as_ushort(lb) << 16);
}

// ------------------------------------------------------------------
__global__ void init_kernel() {
    if (blockIdx.x == 0 && threadIdx.x == 0) g_cnt = 0ULL;
}

__global__ void reduce_nc_kernel(const float* __restrict__ feat) {
    int nc = blockIdx.x;
    const float* base = feat + (size_t)nc * HW;
    int t = threadIdx.x;
    float s = 0.f, m = -3.402823466e38f;
    for (int i = t; i < HW; i += 256) { float v = base[i]; s += v; m = fmaxf(m, v); }
    __shared__ float ss[256], sm[256];
    ss[t] = s; sm[t] = m;
    __syncthreads();
    for (int st = 128; st > 0; st >>= 1) {
        if (t < st) { ss[t] += ss[t + st]; sm[t] = fmaxf(sm[t], sm[t + st]); }
        __syncthreads();
    }
    if (t == 0) { g_avg[nc] = ss[0] * (1.f / HW); g_mx[nc] = sm[0]; }
}

__global__ void reduce_pix_kernel(const float* __restrict__ feat) {
    int p = blockIdx.x * blockDim.x + threadIdx.x;
    if (p >= NP) return;
    int n = p >> 14, pix = p & 16383;
    const float* base = feat + (size_t)n * C_CH * HW + pix;
    float s = 0.f, m = -3.402823466e38f;
    #pragma unroll 8
    for (int c = 0; c < C_CH; c++) { float v = base[(size_t)c * HW]; s += v; m = fmaxf(m, v); }
    g_cmean[p] = s * (1.f / C_CH);
    g_cmax[p] = m;
}

__global__ void chatt_kernel(const float* __restrict__ w1, const float* __restrict__ w2) {
    __shared__ float hs[N_IMG][16];
    int t = threadIdx.x;
    if (t < N_IMG * 16) {
        int n = t / 16, h = t % 16;
        float sa = 0.f, sm = 0.f;
        const float* wr = w1 + h * C_CH;
        const float* av = g_avg + n * C_CH;
        const float* mv = g_mx + n * C_CH;
        for (int c = 0; c < C_CH; c++) { sa += av[c] * wr[c]; sm += mv[c] * wr[c]; }
        hs[n][h] = fmaxf(sa, 0.f) + fmaxf(sm, 0.f);
    }
    __syncthreads();
    for (int idx = t; idx < N_IMG * C_CH; idx += 256) {
        int n = idx >> 8, c = idx & 255;
        float p = 0.f;
        #pragma unroll
        for (int h = 0; h < 16; h++) p += hs[n][h] * w2[c * 16 + h];
        g_chatt[idx] = sigmoidf(p);
    }
}

__global__ void spatial_kernel(const float* __restrict__ sw) {
    int idx = blockIdx.x * blockDim.x + threadIdx.x;
    if (idx >= NP) return;
    int n = idx >> 14, pix = idx & 16383;
    int h = pix >> 7, w = pix & 127;
    float satt = 0.f, act = 0.f;
    #pragma unroll
    for (int ky = 0; ky < 3; ky++) {
        int hh = h + ky - 1;
        if (hh < 0 || hh >= HH) continue;
        #pragma unroll
        for (int kx = 0; kx < 3; kx++) {
            int ww = w + kx - 1;
            if (ww < 0 || ww >= WWID) continue;
            int q = n * HW + hh * WWID + ww;
            float cm = g_cmean[q], cx = g_cmax[q];
            satt += cm * sw[ky * 3 + kx] + cx * sw[9 + ky * 3 + kx];
            act += g2w(ky, kx) * sigmoidf(cm);
        }
    }
    g_spatt[idx] = sigmoidf(satt);
    g_act[idx] = act;
}

__global__ void chcoef_kernel(const float* __restrict__ cfw) {
    __shared__ float ego[C_CH];
    __shared__ float att[4][C_CH];
    __shared__ float tmp[4][C_CH];
    int t = threadIdx.x;
    for (int i = t; i < C_CH; i += 256) ego[i] = 1.f - g_chatt[i];
    for (int i = t; i < 4 * C_CH; i += 256) att[i >> 8][i & 255] = g_chatt[C_CH + i];
    __syncthreads();
    for (int i = t; i < 4 * C_CH; i += 256) {
        int n = i >> 8, c = i & 255;
        const float* row = cfw + (size_t)c * C2;
        float p = 0.f;
        for (int k = 0; k < C_CH; k++) p += ego[k] * row[k] + att[n][k] * row[C_CH + k];
        tmp[n][c] = sigmoidf(p);
    }
    __syncthreads();
    for (int i = t; i < 4 * C_CH; i += 256) {
        int n = i >> 8, c = i & 255;
        float v = G1_C * tmp[n][c];
        if (c > 0)   v += G1_S * tmp[n][c - 1];
        if (c < 255) v += G1_S * tmp[n][c + 1];
        g_chcoef[i] = v;
    }
}

__global__ void spcoef_kernel(const float* __restrict__ spfus) {
    int idx = blockIdx.x * blockDim.x + threadIdx.x;
    if (idx >= 4 * HW) return;
    int m = idx >> 14, pix = idx & 16383;
    int h = pix >> 7, w = pix & 127;
    float wa = spfus[0], wb = spfus[1];
    float acc = 0.f;
    #pragma unroll
    for (int ky = 0; ky < 3; ky++) {
        int hh = h + ky - 1;
        if (hh < 0 || hh >= HH) continue;
        #pragma unroll
        for (int kx = 0; kx < 3; kx++) {
            int ww = w + kx - 1;
            if (ww < 0 || ww >= WWID) continue;
            int q = hh * WWID + ww;
            float pre = wa * (1.f - g_spatt[q]) + wb * g_spatt[(m + 1) * HW + q];
            acc += g2w(ky, kx) * sigmoidf(pre);
        }
    }
    g_spcoef[idx] = acc;
}

__global__ void mask_kernel(const float* __restrict__ feat,
                            float* __restrict__ out_sf, float* __restrict__ out_sm) {
    int t = threadIdx.x;
    unsigned int cnt = 0;
    for (int idx = blockIdx.x * blockDim.x + t; idx < NCHW_TOT; idx += gridDim.x * blockDim.x) {
        int n = idx / (C_CH * HW);
        float f = feat[idx];
        float sf, sm;
        if (n == 0) { sf = f; sm = 1.f; }
        else {
            int rem = idx - n * C_CH * HW;
            int c = rem >> 14, p = rem & 16383;
            int m = n - 1;
            float v = g_chcoef[m * C_CH + c] * g_spcoef[m * HW + p] * g_act[n * HW + p];
            bool mk = v > THRE;
            sf = mk ? f : 0.f; sm = mk ? 1.f : 0.f;
            cnt += mk ? 1u : 0u;
        }
        out_sf[idx] = sf;
        out_sm[idx] = sm;
    }
    __shared__ unsigned int sc[256];
    sc[t] = cnt;
    __syncthreads();
    for (int s = 128; s > 0; s >>= 1) { if (t < s) sc[t] += sc[t + s]; __syncthreads(); }
    if (t == 0) atomicAdd(&g_cnt, (unsigned long long)sc[0]);
}

// ------------------------------------------------------------------
// weight converters (fp16)
__global__ void w2h_kernel(const float* __restrict__ W2) {
    int i = blockIdx.x * blockDim.x + threadIdx.x;
    if (i < C4 * C4) g_W2h[i] = __float2half_rn(W2[i]);
}
__global__ void w1h_kernel(const float* __restrict__ W1) {
    int i = blockIdx.x * blockDim.x + threadIdx.x;
    if (i < C4 * C2) g_W1h[i] = __float2half_rn(W1[i]);
}

// feat + sparse_feature -> fp16 hi/lo (once)
__global__ void fsplit_kernel(const float* __restrict__ feat, const float* __restrict__ sf) {
    size_t i4 = (size_t)blockIdx.x * blockDim.x + threadIdx.x;
    if (i4 >= (size_t)NCHW_TOT / 4) return;
    size_t e = i4 * 4;
    float4 f = *(const float4*)(feat + e);
    float4 s = *(const float4*)(sf + e);
    uint32_t h0, l0, h1, l1;
    split2h(f.x, f.y, h0, l0); split2h(f.z, f.w, h1, l1);
    *(uint2*)&g_Fhi[e] = make_uint2(h0, h1);
    *(uint2*)&g_Flo[e] = make_uint2(l0, l1);
    split2h(s.x, s.y, h0, l0); split2h(s.z, s.w, h1, l1);
    *(uint2*)&g_Shi[e] = make_uint2(h0, h1);
    *(uint2*)&g_Slo[e] = make_uint2(l0, l1);
}

// z = relu(U[roll]+V+b1) -> fp16 hi/lo, both rolls (once)
__global__ void zprep_kernel(const float* __restrict__ b1) {
    size_t i4 = (size_t)blockIdx.x * blockDim.x + threadIdx.x;
    if (i4 >= (size_t)NP * C4 / 4) return;
    size_t e = i4 * 4;
    int k = (int)(e & 1023);
    size_t p = e >> 10;
    int n = (int)(p >> 14), pix = (int)(p & 16383);
    int nr = (n + 1 == N_IMG) ? 0 : n + 1;
    size_t pr = ((size_t)nr << 14) | pix;
    float4 u  = *(const float4*)(g_U + e);
    float4 ur = *(const float4*)(g_U + (pr << 10) + k);
    float4 v  = *(const float4*)(g_V + e);
    float4 bb = *(const float4*)(b1 + k);
    float4 zT, zP;
    zT.x = fmaxf(u.x + v.x + bb.x, 0.f);  zP.x = fmaxf(ur.x + v.x + bb.x, 0.f);
    zT.y = fmaxf(u.y + v.y + bb.y, 0.f);  zP.y = fmaxf(ur.y + v.y + bb.y, 0.f);
    zT.z = fmaxf(u.z + v.z + bb.z, 0.f);  zP.z = fmaxf(ur.z + v.z + bb.z, 0.f);
    zT.w = fmaxf(u.w + v.w + bb.w, 0.f);  zP.w = fmaxf(ur.w + v.w + bb.w, 0.f);
    uint32_t h0, l0, h1, l1;
    split2h(zT.x, zT.y, h0, l0); split2h(zT.z, zT.w, h1, l1);
    *(uint2*)&g_ZThi[e] = make_uint2(h0, h1);
    *(uint2*)&g_ZTlo[e] = make_uint2(l0, l1);
    split2h(zP.x, zP.y, h0, l0); split2h(zP.z, zP.w, h1, l1);
    *(uint2*)&g_ZPhi[e] = make_uint2(h0, h1);
    *(uint2*)&g_ZPlo[e] = make_uint2(l0, l1);
}

// ==================================================================
// GEMM1 (mma.sync fp16, A split 2-term): Out[p][j] = sum_c A[n][c][p] * W1[j][wcol+c]
// A smem: [k=32][m=128] rows of 272B. B smem: [n=128][k=32] rows 80B.
#define G1_A_HI 0
#define G1_A_LO 8704
#define G1_B_HI 17408
#define G1_STAGE 27648
__global__ __launch_bounds__(256, 1) void gemm1_mma() {
    extern __shared__ __align__(16) char sm1[];
    const int tid = threadIdx.x;
    const int wid = tid >> 5, lane = tid & 31;
    const int wm = wid & 3, wn = wid >> 2;
    const int g = lane >> 2, t2 = (lane & 3) * 2;
    const int jt = blockIdx.x;                 // 0..7
    const size_t P0 = (size_t)blockIdx.y * 128;
    const int which = blockIdx.z;              // 0: U from feat, 1: V from sparse
    const int n = (int)(P0 >> 14), pl = (int)(P0 & 16383);
    const __half* Ah = (which ? g_Shi : g_Fhi) + (size_t)n * C_CH * HW + pl;
    const __half* Al = (which ? g_Slo : g_Flo) + (size_t)n * C_CH * HW + pl;
    const __half* Bh = g_W1h + (size_t)jt * 128 * C2 + (which ? 256 : 0);
    float* Out = which ? g_V : g_U;
    const uint32_t sb = smem_u32(sm1);

    float acc[2][8][4];
    #pragma unroll
    for (int a = 0; a < 2; a++)
        #pragma unroll
        for (int b = 0; b < 8; b++)
            #pragma unroll
            for (int c = 0; c < 4; c++) acc[a][b][c] = 0.f;

    uint4 ph[2], pl2[2], pw[2];
    // prefetch + store chunk 0
    {
        #pragma unroll
        for (int i = 0; i < 2; i++) {
            int s = tid + 256 * i;
            int r = s >> 4, q = s & 15;
            ph[i]  = *(const uint4*)(Ah + (size_t)r * HW + q * 8);
            pl2[i] = *(const uint4*)(Al + (size_t)r * HW + q * 8);
            int o = s >> 2, qq = s & 3;
            pw[i] = *(const uint4*)(Bh + (size_t)o * C2 + qq * 8);
        }
        char* buf = sm1;
        #pragma unroll
        for (int i = 0; i < 2; i++) {
            int s = tid + 256 * i;
            int r = s >> 4, q = s & 15;
            *(uint4*)(buf + G1_A_HI + r * 272 + q * 16) = ph[i];
            *(uint4*)(buf + G1_A_LO + r * 272 + q * 16) = pl2[i];
            int o = s >> 2, qq = s & 3;
            *(uint4*)(buf + G1_B_HI + o * 80 + qq * 16) = pw[i];
        }
    }
    __syncthreads();

    for (int kc = 0; kc < 8; kc++) {
        if (kc + 1 < 8) {
            int k0 = (kc + 1) * 32;
            #pragma unroll
            for (int i = 0; i < 2; i++) {
                int s = tid + 256 * i;
                int r = s >> 4, q = s & 15;
                ph[i]  = *(const uint4*)(Ah + (size_t)(k0 + r) * HW + q * 8);
                pl2[i] = *(const uint4*)(Al + (size_t)(k0 + r) * HW + q * 8);
                int o = s >> 2, qq = s & 3;
                pw[i] = *(const uint4*)(Bh + (size_t)o * C2 + k0 + qq * 8);
            }
        }
        const uint32_t base = sb + (kc & 1) * G1_STAGE;
        #pragma unroll
        for (int ks = 0; ks < 2; ks++) {
            uint32_t bh[8][2];
            #pragma unroll
            for (int np = 0; np < 4; np++) {
                int row = wn * 64 + np * 16 + (lane & 7) + ((lane >> 4) & 1) * 8;
                uint32_t col = ks * 32 + ((lane >> 3) & 1) * 16;
                uint32_t a = base + G1_B_HI + row * 80 + col;
                ldsm4(bh[2 * np][0], bh[2 * np][1], bh[2 * np + 1][0], bh[2 * np + 1][1], a);
            }
            #pragma unroll
            for (int mf = 0; mf < 2; mf++) {
                int rowk = ks * 16 + ((lane >> 4) & 1) * 8 + (lane & 7);
                uint32_t col = (wm * 32 + mf * 16 + ((lane >> 3) & 1) * 8) * 2;
                uint32_t a = base + G1_A_HI + rowk * 272 + col;
                uint32_t ah0, ah1, ah2, ah3, al0, al1, al2, al3;
                ldsm4t(ah0, ah1, ah2, ah3, a);
                ldsm4t(al0, al1, al2, al3, a + (G1_A_LO - G1_A_HI));
                #pragma unroll
                for (int nf = 0; nf < 8; nf++) {
                    mma_f16(acc[mf][nf], ah0, ah1, ah2, ah3, bh[nf][0], bh[nf][1]);
                    mma_f16(acc[mf][nf], al0, al1, al2, al3, bh[nf][0], bh[nf][1]);
                }
            }
        }
        if (kc + 1 < 8) {
            char* buf = sm1 + ((kc + 1) & 1) * G1_STAGE;
            #pragma unroll
            for (int i = 0; i < 2; i++) {
                int s = tid + 256 * i;
                int r = s >> 4, q = s & 15;
                *(uint4*)(buf + G1_A_HI + r * 272 + q * 16) = ph[i];
                *(uint4*)(buf + G1_A_LO + r * 272 + q * 16) = pl2[i];
                int o = s >> 2, qq = s & 3;
                *(uint4*)(buf + G1_B_HI + o * 80 + qq * 16) = pw[i];
            }
        }
        __syncthreads();
    }

    // write Out fp32 [p][j]
    #pragma unroll
    for (int mf = 0; mf < 2; mf++) {
        #pragma unroll
        for (int nf = 0; nf < 8; nf++) {
            size_t r0 = P0 + wm * 32 + mf * 16 + g;
            int col = jt * 128 + wn * 64 + nf * 8 + t2;
            *(float2*)&Out[r0 * C4 + col] = make_float2(acc[mf][nf][0], acc[mf][nf][1]);
            *(float2*)&Out[(r0 + 8) * C4 + col] = make_float2(acc[mf][nf][2], acc[mf][nf][3]);
        }
    }
}

// ==================================================================
// GEMM2 (mma.sync fp16, A split 2-term, light loader, fused epilogue):
// T[p] = sum_o relu( (z @ W2^T)[p][o] + b2[o] ) * w3[o]
// A smem: [m=128][k=32] rows 80B; B smem: [o=128][k=32] rows 80B.
#define G2_A_HI 0
#define G2_A_LO 10240
#define G2_B_HI 20480
#define G2_STAGE 30720
__global__ __launch_bounds__(256, 1) void gemm2_mma(const float* __restrict__ b2,
                                                    const float* __restrict__ w3) {
    extern __shared__ __align__(16) char sm2[];
    const int tid = threadIdx.x;
    const int wid = tid >> 5, lane = tid & 31;
    const int wm = wid & 3, wn = wid >> 2;
    const int g = lane >> 2, t2 = (lane & 3) * 2;
    const size_t P0 = (size_t)blockIdx.x * 128;
    const int roll = blockIdx.y;
    const __half* Zh = (roll ? g_ZPhi : g_ZThi) + P0 * C4;
    const __half* Zl = (roll ? g_ZPlo : g_ZTlo) + P0 * C4;
    float* tOut = roll ? g_tP : g_tT;
    const uint32_t sb = smem_u32(sm2);

    float sAcc[4] = {0.f, 0.f, 0.f, 0.f};

    for (int nt = 0; nt < 8; nt++) {
        const int o0 = nt * 128;
        const __half* Wh = g_W2h + (size_t)o0 * C4;
        float acc[2][8][4];
        #pragma unroll
        for (int a = 0; a < 2; a++)
            #pragma unroll
            for (int b = 0; b < 8; b++)
                #pragma unroll
                for (int c = 0; c < 4; c++) acc[a][b][c] = 0.f;

        uint4 pah[2], pal[2], pw[2];
        // prefetch + store chunk 0
        {
            #pragma unroll
            for (int i = 0; i < 2; i++) {
                int s = tid + 256 * i;
                int p = s >> 2, q = s & 3;
                pah[i] = *(const uint4*)(Zh + (size_t)p * C4 + q * 8);
                pal[i] = *(const uint4*)(Zl + (size_t)p * C4 + q * 8);
                pw[i]  = *(const uint4*)(Wh + (size_t)p * C4 + q * 8);
            }
            char* buf = sm2;
            #pragma unroll
            for (int i = 0; i < 2; i++) {
                int s = tid + 256 * i;
                int p = s >> 2, q = s & 3;
                *(uint4*)(buf + G2_A_HI + p * 80 + q * 16) = pah[i];
                *(uint4*)(buf + G2_A_LO + p * 80 + q * 16) = pal[i];
                *(uint4*)(buf + G2_B_HI + p * 80 + q * 16) = pw[i];
            }
        }
        __syncthreads();

        for (int kc = 0; kc < 32; kc++) {
            if (kc + 1 < 32) {
                int k0 = (kc + 1) * 32;
                #pragma unroll
                for (int i = 0; i < 2; i++) {
                    int s = tid + 256 * i;
                    int p = s >> 2, q = s & 3;
                    pah[i] = *(const uint4*)(Zh + (size_t)p * C4 + k0 + q * 8);
                    pal[i] = *(const uint4*)(Zl + (size_t)p * C4 + k0 + q * 8);
                    pw[i]  = *(const uint4*)(Wh + (size_t)p * C4 + k0 + q * 8);
                }
            }
            const uint32_t base = sb + (kc & 1) * G2_STAGE;
            #pragma unroll
            for (int ks = 0; ks < 2; ks++) {
                uint32_t bh[8][2];
                #pragma unroll
                for (int np = 0; np < 4; np++) {
                    int row = wn * 64 + np * 16 + (lane & 7) + ((lane >> 4) & 1) * 8;
                    uint32_t col = ks * 32 + ((lane >> 3) & 1) * 16;
                    uint32_t a = base + G2_B_HI + row * 80 + col;
                    ldsm4(bh[2 * np][0], bh[2 * np][1], bh[2 * np + 1][0], bh[2 * np + 1][1], a);
                }
                #pragma unroll
                for (int mf = 0; mf < 2; mf++) {
                    int row = wm * 32 + mf * 16 + (lane & 7) + ((lane >> 3) & 1) * 8;
                    uint32_t col = ks * 32 + ((lane >> 4) & 1) * 16;
                    uint32_t a = base + G2_A_HI + row * 80 + col;
                    uint32_t ah0, ah1, ah2, ah3, al0, al1, al2, al3;
                    ldsm4(ah0, ah1, ah2, ah3, a);
                    ldsm4(al0, al1, al2, al3, a + (G2_A_LO - G2_A_HI));
                    #pragma unroll
                    for (int nf = 0; nf < 8; nf++) {
                        mma_f16(acc[mf][nf], ah0, ah1, ah2, ah3, bh[nf][0], bh[nf][1]);
                        mma_f16(acc[mf][nf], al0, al1, al2, al3, bh[nf][0], bh[nf][1]);
                    }
                }
            }
            if (kc + 1 < 32) {
                char* buf = sm2 + ((kc + 1) & 1) * G2_STAGE;
                #pragma unroll
                for (int i = 0; i < 2; i++) {
                    int s = tid + 256 * i;
                    int p = s >> 2, q = s & 3;
                    *(uint4*)(buf + G2_A_HI + p * 80 + q * 16) = pah[i];
                    *(uint4*)(buf + G2_A_LO + p * 80 + q * 16) = pal[i];
                    *(uint4*)(buf + G2_B_HI + p * 80 + q * 16) = pw[i];
                }
            }
            __syncthreads();
        }

        // fold this n-tile into per-pixel scalars
        #pragma unroll
        for (int mf = 0; mf < 2; mf++) {
            #pragma unroll
            for (int nf = 0; nf < 8; nf++) {
                int c0 = o0 + wn * 64 + nf * 8 + t2;
                float b2a = __ldg(b2 + c0), b2b = __ldg(b2 + c0 + 1);
                float w3a = __ldg(w3 + c0), w3b = __ldg(w3 + c0 + 1);
                sAcc[mf * 2 + 0] += fmaxf(acc[mf][nf][0] + b2a, 0.f) * w3a
                                  + fmaxf(acc[mf][nf][1] + b2b, 0.f) * w3b;
                sAcc[mf * 2 + 1] += fmaxf(acc[mf][nf][2] + b2a, 0.f) * w3a
                                  + fmaxf(acc[mf][nf][3] + b2b, 0.f) * w3b;
            }
        }
    }

    // reduce across the 4-lane groups (same rows, different cols)
    #pragma unroll
    for (int i = 0; i < 4; i++) {
        sAcc[i] += __shfl_xor_sync(0xFFFFFFFFu, sAcc[i], 1);
        sAcc[i] += __shfl_xor_sync(0xFFFFFFFFu, sAcc[i], 2);
    }
    __syncthreads();
    float* sRed = (float*)sm2;   // reuse smem: [2][128]
    if ((lane & 3) == 0) {
        #pragma unroll
        for (int i = 0; i < 4; i++) {
            int r = wm * 32 + (i >> 1) * 16 + (i & 1) * 8 + g;
            sRed[wn * 128 + r] = sAcc[i];
        }
    }
    __syncthreads();
    if (tid < 128) tOut[P0 + tid] = sRed[tid] + sRed[128 + tid];
}

// ------------------------------------------------------------------
__global__ void loss_kernel(const float* __restrict__ st_b3, float* __restrict__ out) {
    __shared__ double red[256];
    int t = threadIdx.x;
    float b3 = st_b3[0];
    double s = 0.0;
    for (int i = t; i < NP; i += 256) {
        float tt = g_tT[i] + b3;
        float tp = g_tP[i] + b3;
        s += (double)softplusf(-tt) + (double)softplusf(tp);
    }
    red[t] = s;
    __syncthreads();
    for (int st = 128; st > 0; st >>= 1) { if (t < st) red[t] += red[t + st]; __syncthreads(); }
    if (t == 0) {
        out[LOSS_IDX] = (float)(red[0] / 81920.0);
        out[RATE_IDX] = (float)((double)g_cnt / 16777216.0);
    }
}

// ------------------------------------------------------------------
extern "C" void kernel_launch(void* const* d_in, const int* in_sizes, int n_in,
                              void* d_out, int out_size) {
    const float* feat     = (const float*)d_in[0];
    const float* mlp_w1   = (const float*)d_in[1];
    const float* mlp_w2   = (const float*)d_in[2];
    const float* sp_req_w = (const float*)d_in[3];
    const float* ch_fus_w = (const float*)d_in[4];
    const float* sp_fus_w = (const float*)d_in[5];
    const float* st_w1    = (const float*)d_in[6];
    const float* st_b1    = (const float*)d_in[7];
    const float* st_w2    = (const float*)d_in[8];
    const float* st_b2    = (const float*)d_in[9];
    const float* st_w3    = (const float*)d_in[10];
    const float* st_b3    = (const float*)d_in[11];

    float* out = (float*)d_out;
    float* out_sf = out;
    float* out_sm = out + SM_OFF;

    cudaFuncSetAttribute(gemm1_mma, cudaFuncAttributeMaxDynamicSharedMemorySize, 2 * G1_STAGE);
    cudaFuncSetAttribute(gemm2_mma, cudaFuncAttributeMaxDynamicSharedMemorySize, 2 * G2_STAGE);

    init_kernel<<<1, 32>>>();
    reduce_nc_kernel<<<N_IMG * C_CH, 256>>>(feat);
    reduce_pix_kernel<<<(NP + 255) / 256, 256>>>(feat);
    chatt_kernel<<<1, 256>>>(mlp_w1, mlp_w2);
    spatial_kernel<<<(NP + 255) / 256, 256>>>(sp_req_w);
    chcoef_kernel<<<1, 256>>>(ch_fus_w);
    spcoef_kernel<<<(4 * HW + 255) / 256, 256>>>(sp_fus_w);
    mask_kernel<<<2048, 256>>>(feat, out_sf, out_sm);

    w1h_kernel<<<(C4 * C2 + 255) / 256, 256>>>(st_w1);
    w2h_kernel<<<(C4 * C4 + 255) / 256, 256>>>(st_w2);
    fsplit_kernel<<<(NCHW_TOT / 4 + 255) / 256, 256>>>(feat, out_sf);

    dim3 g1grid(8, NP / 128, 2);
    gemm1_mma<<<g1grid, 256, 2 * G1_STAGE>>>();

    zprep_kernel<<<(int)(((size_t)NP * C4 / 4 + 255) / 256), 256>>>(st_b1);

    dim3 g2grid(NP / 128, 2);
    gemm2_mma<<<g2grid, 256, 2 * G2_STAGE>>>(st_b2, st_w3);

    loss_kernel<<<1, 256>>>(st_b3, out);
}

// round 6
// speedup vs baseline: 6.9329x; 1.5767x over previous
#include <cuda_runtime.h>
#include <cuda_fp16.h>
#include <cstdint>
#include <math.h>

// ---- problem constants ----
#define N_IMG 5
#define C_CH  256
#define HH    128
#define WWID  128
#define HW    16384
#define NP    81920            // N_IMG * HW
#define C4    1024             // 4*C
#define C2    512              // 2*C
#define THRE  0.01f
#define NCHW_TOT (N_IMG * C_CH * HW)

// output layout: [sparse_feature | loss | rate | sparse_mask]
#define LOSS_IDX 20971520
#define RATE_IDX 20971521
#define SM_OFF   20971522

// gaussian weights
#define G2_C 0.15915494309189535f
#define G2_E 0.09653235263005391f
#define G2_D 0.05855018091964769f
#define G1_C 0.45186276187760605f
#define G1_S 0.27406861906119697f

// ---- device scratch ----
__device__ __align__(16) float g_U[(size_t)NP * C4];
__device__ __align__(16) float g_V[(size_t)NP * C4];
__device__ __align__(16) __half g_ZT[(size_t)NP * C4];
__device__ __align__(16) __half g_ZP[(size_t)NP * C4];
__device__ __align__(16) __half g_Fh[(size_t)NCHW_TOT];
__device__ __align__(16) __half g_Sh[(size_t)NCHW_TOT];
__device__ __align__(16) __half g_W2h[(size_t)C4 * C4];
__device__ __align__(16) __half g_W1h[(size_t)C4 * C2];
__device__ float g_avg[N_IMG * C_CH];
__device__ float g_mx[N_IMG * C_CH];
__device__ float g_chatt[N_IMG * C_CH];
__device__ float g_chcoef[4 * C_CH];
__device__ float g_cmean[NP];
__device__ float g_cmax[NP];
__device__ float g_spatt[NP];
__device__ float g_act[NP];
__device__ float g_spcoef[4 * HW];
__device__ float g_tT[NP];
__device__ float g_tP[NP];
__device__ unsigned long long g_cnt;

__device__ __forceinline__ float sigmoidf(float x) { return 1.f / (1.f + expf(-x)); }
__device__ __forceinline__ float softplusf(float x) { return fmaxf(x, 0.f) + log1pf(expf(-fabsf(x))); }
__device__ __forceinline__ float g2w(int ky, int kx) {
    int d = (ky != 1) + (kx != 1);
    return d == 0 ? G2_C : (d == 1 ? G2_E : G2_D);
}

// ================= mma.sync helpers =================
__device__ __forceinline__ uint32_t smem_u32(const void* p) {
    uint32_t a;
    asm("{ .reg .u64 t; cvta.to.shared.u64 t, %1; cvt.u32.u64 %0, t; }" : "=r"(a) : "l"(p));
    return a;
}
__device__ __forceinline__ void ldsm4(uint32_t& r0, uint32_t& r1, uint32_t& r2, uint32_t& r3, uint32_t a) {
    asm volatile("ldmatrix.sync.aligned.m8n8.x4.shared.b16 {%0,%1,%2,%3}, [%4];"
                 : "=r"(r0), "=r"(r1), "=r"(r2), "=r"(r3) : "r"(a));
}
__device__ __forceinline__ void ldsm4t(uint32_t& r0, uint32_t& r1, uint32_t& r2, uint32_t& r3, uint32_t a) {
    asm volatile("ldmatrix.sync.aligned.m8n8.x4.trans.shared.b16 {%0,%1,%2,%3}, [%4];"
                 : "=r"(r0), "=r"(r1), "=r"(r2), "=r"(r3) : "r"(a));
}
__device__ __forceinline__ void mma_f16(float* c, uint32_t a0, uint32_t a1, uint32_t a2, uint32_t a3,
                                        uint32_t b0, uint32_t b1) {
    asm volatile("mma.sync.aligned.m16n8k16.row.col.f32.f16.f16.f32 "
                 "{%0,%1,%2,%3}, {%4,%5,%6,%7}, {%8,%9}, {%0,%1,%2,%3};"
                 : "+f"(c[0]), "+f"(c[1]), "+f"(c[2]), "+f"(c[3])
                 : "r"(a0), "r"(a1), "r"(a2), "r"(a3), "r"(b0), "r"(b1));
}
__device__ __forceinline__ uint32_t pack2h(float a, float b) {
    __half ha = __float2half_rn(a);
    __half hb = __float2half_rn(b);
    return (uint32_t)__half_as_ushort(ha) | ((uint32_t)__half_as_ushort(hb) << 16);
}

// ------------------------------------------------------------------
__global__ void init_kernel() {
    if (blockIdx.x == 0 && threadIdx.x == 0) g_cnt = 0ULL;
}

__global__ void reduce_nc_kernel(const float* __restrict__ feat) {
    int nc = blockIdx.x;
    const float* base = feat + (size_t)nc * HW;
    int t = threadIdx.x;
    float s = 0.f, m = -3.402823466e38f;
    for (int i = t; i < HW; i += 256) { float v = base[i]; s += v; m = fmaxf(m, v); }
    __shared__ float ss[256], sm[256];
    ss[t] = s; sm[t] = m;
    __syncthreads();
    for (int st = 128; st > 0; st >>= 1) {
        if (t < st) { ss[t] += ss[t + st]; sm[t] = fmaxf(sm[t], sm[t + st]); }
        __syncthreads();
    }
    if (t == 0) { g_avg[nc] = ss[0] * (1.f / HW); g_mx[nc] = sm[0]; }
}

__global__ void reduce_pix_kernel(const float* __restrict__ feat) {
    int p = blockIdx.x * blockDim.x + threadIdx.x;
    if (p >= NP) return;
    int n = p >> 14, pix = p & 16383;
    const float* base = feat + (size_t)n * C_CH * HW + pix;
    float s = 0.f, m = -3.402823466e38f;
    #pragma unroll 8
    for (int c = 0; c < C_CH; c++) { float v = base[(size_t)c * HW]; s += v; m = fmaxf(m, v); }
    g_cmean[p] = s * (1.f / C_CH);
    g_cmax[p] = m;
}

__global__ void chatt_kernel(const float* __restrict__ w1, const float* __restrict__ w2) {
    __shared__ float hs[N_IMG][16];
    int t = threadIdx.x;
    if (t < N_IMG * 16) {
        int n = t / 16, h = t % 16;
        float sa = 0.f, sm = 0.f;
        const float* wr = w1 + h * C_CH;
        const float* av = g_avg + n * C_CH;
        const float* mv = g_mx + n * C_CH;
        for (int c = 0; c < C_CH; c++) { sa += av[c] * wr[c]; sm += mv[c] * wr[c]; }
        hs[n][h] = fmaxf(sa, 0.f) + fmaxf(sm, 0.f);
    }
    __syncthreads();
    for (int idx = t; idx < N_IMG * C_CH; idx += 256) {
        int n = idx >> 8, c = idx & 255;
        float p = 0.f;
        #pragma unroll
        for (int h = 0; h < 16; h++) p += hs[n][h] * w2[c * 16 + h];
        g_chatt[idx] = sigmoidf(p);
    }
}

__global__ void spatial_kernel(const float* __restrict__ sw) {
    int idx = blockIdx.x * blockDim.x + threadIdx.x;
    if (idx >= NP) return;
    int n = idx >> 14, pix = idx & 16383;
    int h = pix >> 7, w = pix & 127;
    float satt = 0.f, act = 0.f;
    #pragma unroll
    for (int ky = 0; ky < 3; ky++) {
        int hh = h + ky - 1;
        if (hh < 0 || hh >= HH) continue;
        #pragma unroll
        for (int kx = 0; kx < 3; kx++) {
            int ww = w + kx - 1;
            if (ww < 0 || ww >= WWID) continue;
            int q = n * HW + hh * WWID + ww;
            float cm = g_cmean[q], cx = g_cmax[q];
            satt += cm * sw[ky * 3 + kx] + cx * sw[9 + ky * 3 + kx];
            act += g2w(ky, kx) * sigmoidf(cm);
        }
    }
    g_spatt[idx] = sigmoidf(satt);
    g_act[idx] = act;
}

__global__ void chcoef_kernel(const float* __restrict__ cfw) {
    __shared__ float ego[C_CH];
    __shared__ float att[4][C_CH];
    __shared__ float tmp[4][C_CH];
    int t = threadIdx.x;
    for (int i = t; i < C_CH; i += 256) ego[i] = 1.f - g_chatt[i];
    for (int i = t; i < 4 * C_CH; i += 256) att[i >> 8][i & 255] = g_chatt[C_CH + i];
    __syncthreads();
    for (int i = t; i < 4 * C_CH; i += 256) {
        int n = i >> 8, c = i & 255;
        const float* row = cfw + (size_t)c * C2;
        float p = 0.f;
        for (int k = 0; k < C_CH; k++) p += ego[k] * row[k] + att[n][k] * row[C_CH + k];
        tmp[n][c] = sigmoidf(p);
    }
    __syncthreads();
    for (int i = t; i < 4 * C_CH; i += 256) {
        int n = i >> 8, c = i & 255;
        float v = G1_C * tmp[n][c];
        if (c > 0)   v += G1_S * tmp[n][c - 1];
        if (c < 255) v += G1_S * tmp[n][c + 1];
        g_chcoef[i] = v;
    }
}

__global__ void spcoef_kernel(const float* __restrict__ spfus) {
    int idx = blockIdx.x * blockDim.x + threadIdx.x;
    if (idx >= 4 * HW) return;
    int m = idx >> 14, pix = idx & 16383;
    int h = pix >> 7, w = pix & 127;
    float wa = spfus[0], wb = spfus[1];
    float acc = 0.f;
    #pragma unroll
    for (int ky = 0; ky < 3; ky++) {
        int hh = h + ky - 1;
        if (hh < 0 || hh >= HH) continue;
        #pragma unroll
        for (int kx = 0; kx < 3; kx++) {
            int ww = w + kx - 1;
            if (ww < 0 || ww >= WWID) continue;
            int q = hh * WWID + ww;
            float pre = wa * (1.f - g_spatt[q]) + wb * g_spatt[(m + 1) * HW + q];
            acc += g2w(ky, kx) * sigmoidf(pre);
        }
    }
    g_spcoef[idx] = acc;
}

// mask + sparse_feature + sparse_mask + fp16 copies of feat & sparse (fused)
__global__ void mask_kernel(const float* __restrict__ feat,
                            float* __restrict__ out_sf, float* __restrict__ out_sm) {
    int t = threadIdx.x;
    unsigned int cnt = 0;
    for (int i2 = blockIdx.x * blockDim.x + t; i2 < NCHW_TOT / 2; i2 += gridDim.x * blockDim.x) {
        int idx = i2 * 2;
        int n = idx / (C_CH * HW);
        float2 f = *(const float2*)(feat + idx);
        float2 sf, sm;
        if (n == 0) { sf = f; sm = make_float2(1.f, 1.f); }
        else {
            int rem = idx - n * C_CH * HW;
            int c = rem >> 14, p = rem & 16383;
            int m = n - 1;
            float cc = g_chcoef[m * C_CH + c];
            float v0 = cc * g_spcoef[m * HW + p] * g_act[n * HW + p];
            float v1 = cc * g_spcoef[m * HW + p + 1] * g_act[n * HW + p + 1];
            bool mk0 = v0 > THRE, mk1 = v1 > THRE;
            sf.x = mk0 ? f.x : 0.f; sm.x = mk0 ? 1.f : 0.f;
            sf.y = mk1 ? f.y : 0.f; sm.y = mk1 ? 1.f : 0.f;
            cnt += (mk0 ? 1u : 0u) + (mk1 ? 1u : 0u);
        }
        *(float2*)(out_sf + idx) = sf;
        *(float2*)(out_sm + idx) = sm;
        *(uint32_t*)&g_Fh[idx] = pack2h(f.x, f.y);
        *(uint32_t*)&g_Sh[idx] = pack2h(sf.x, sf.y);
    }
    __shared__ unsigned int sc[256];
    sc[t] = cnt;
    __syncthreads();
    for (int s = 128; s > 0; s >>= 1) { if (t < s) sc[t] += sc[t + s]; __syncthreads(); }
    if (t == 0) atomicAdd(&g_cnt, (unsigned long long)sc[0]);
}

// ------------------------------------------------------------------
// weight converters (fp16)
__global__ void w2h_kernel(const float* __restrict__ W2) {
    int i = blockIdx.x * blockDim.x + threadIdx.x;
    if (i < C4 * C4) g_W2h[i] = __float2half_rn(W2[i]);
}
__global__ void w1h_kernel(const float* __restrict__ W1) {
    int i = blockIdx.x * blockDim.x + threadIdx.x;
    if (i < C4 * C2) g_W1h[i] = __float2half_rn(W1[i]);
}

// z = relu(U[roll]+V+b1) -> fp16, both rolls (once)
__global__ void zprep_kernel(const float* __restrict__ b1) {
    size_t i4 = (size_t)blockIdx.x * blockDim.x + threadIdx.x;
    if (i4 >= (size_t)NP * C4 / 4) return;
    size_t e = i4 * 4;
    int k = (int)(e & 1023);
    size_t p = e >> 10;
    int n = (int)(p >> 14), pix = (int)(p & 16383);
    int nr = (n + 1 == N_IMG) ? 0 : n + 1;
    size_t pr = ((size_t)nr << 14) | pix;
    float4 u  = *(const float4*)(g_U + e);
    float4 ur = *(const float4*)(g_U + (pr << 10) + k);
    float4 v  = *(const float4*)(g_V + e);
    float4 bb = *(const float4*)(b1 + k);
    uint2 zt, zp;
    zt.x = pack2h(fmaxf(u.x + v.x + bb.x, 0.f), fmaxf(u.y + v.y + bb.y, 0.f));
    zt.y = pack2h(fmaxf(u.z + v.z + bb.z, 0.f), fmaxf(u.w + v.w + bb.w, 0.f));
    zp.x = pack2h(fmaxf(ur.x + v.x + bb.x, 0.f), fmaxf(ur.y + v.y + bb.y, 0.f));
    zp.y = pack2h(fmaxf(ur.z + v.z + bb.z, 0.f), fmaxf(ur.w + v.w + bb.w, 0.f));
    *(uint2*)&g_ZT[e] = zt;
    *(uint2*)&g_ZP[e] = zp;
}

// ==================================================================
// GEMM1 (mma.sync fp16): Out[p][j] = sum_c A[n][c][p] * W1[j][wcol+c]
// A smem: [k=32][m=128] rows of 272B. B smem: [n=128][k=32] rows 80B.
#define G1_A_OF 0
#define G1_B_OF 8704
#define G1_STAGE 18944
__global__ __launch_bounds__(256, 2) void gemm1_mma() {
    extern __shared__ __align__(16) char sm1[];
    const int tid = threadIdx.x;
    const int wid = tid >> 5, lane = tid & 31;
    const int wm = wid & 3, wn = wid >> 2;
    const int g = lane >> 2, t2 = (lane & 3) * 2;
    const int jt = blockIdx.x;                 // 0..7
    const size_t P0 = (size_t)blockIdx.y * 128;
    const int which = blockIdx.z;              // 0: U from feat, 1: V from sparse
    const int n = (int)(P0 >> 14), pl = (int)(P0 & 16383);
    const __half* Ah = (which ? g_Sh : g_Fh) + (size_t)n * C_CH * HW + pl;
    const __half* Bh = g_W1h + (size_t)jt * 128 * C2 + (which ? 256 : 0);
    float* Out = which ? g_V : g_U;
    const uint32_t sb = smem_u32(sm1);

    float acc[2][8][4];
    #pragma unroll
    for (int a = 0; a < 2; a++)
        #pragma unroll
        for (int b = 0; b < 8; b++)
            #pragma unroll
            for (int c = 0; c < 4; c++) acc[a][b][c] = 0.f;

    uint4 pa[2], pw[2];
    {
        #pragma unroll
        for (int i = 0; i < 2; i++) {
            int s = tid + 256 * i;
            int r = s >> 4, q = s & 15;
            pa[i] = *(const uint4*)(Ah + (size_t)r * HW + q * 8);
            int o = s >> 2, qq = s & 3;
            pw[i] = *(const uint4*)(Bh + (size_t)o * C2 + qq * 8);
        }
        char* buf = sm1;
        #pragma unroll
        for (int i = 0; i < 2; i++) {
            int s = tid + 256 * i;
            int r = s >> 4, q = s & 15;
            *(uint4*)(buf + G1_A_OF + r * 272 + q * 16) = pa[i];
            int o = s >> 2, qq = s & 3;
            *(uint4*)(buf + G1_B_OF + o * 80 + qq * 16) = pw[i];
        }
    }
    __syncthreads();

    for (int kc = 0; kc < 8; kc++) {
        if (kc + 1 < 8) {
            int k0 = (kc + 1) * 32;
            #pragma unroll
            for (int i = 0; i < 2; i++) {
                int s = tid + 256 * i;
                int r = s >> 4, q = s & 15;
                pa[i] = *(const uint4*)(Ah + (size_t)(k0 + r) * HW + q * 8);
                int o = s >> 2, qq = s & 3;
                pw[i] = *(const uint4*)(Bh + (size_t)o * C2 + k0 + qq * 8);
            }
        }
        const uint32_t base = sb + (kc & 1) * G1_STAGE;
        #pragma unroll
        for (int ks = 0; ks < 2; ks++) {
            uint32_t bh[8][2];
            #pragma unroll
            for (int np = 0; np < 4; np++) {
                int row = wn * 64 + np * 16 + (lane & 7) + ((lane >> 4) & 1) * 8;
                uint32_t col = ks * 32 + ((lane >> 3) & 1) * 16;
                uint32_t a = base + G1_B_OF + row * 80 + col;
                ldsm4(bh[2 * np][0], bh[2 * np][1], bh[2 * np + 1][0], bh[2 * np + 1][1], a);
            }
            #pragma unroll
            for (int mf = 0; mf < 2; mf++) {
                int rowk = ks * 16 + ((lane >> 4) & 1) * 8 + (lane & 7);
                uint32_t col = (wm * 32 + mf * 16 + ((lane >> 3) & 1) * 8) * 2;
                uint32_t a = base + G1_A_OF + rowk * 272 + col;
                uint32_t a0, a1, a2, a3;
                ldsm4t(a0, a1, a2, a3, a);
                #pragma unroll
                for (int nf = 0; nf < 8; nf++)
                    mma_f16(acc[mf][nf], a0, a1, a2, a3, bh[nf][0], bh[nf][1]);
            }
        }
        if (kc + 1 < 8) {
            char* buf = sm1 + ((kc + 1) & 1) * G1_STAGE;
            #pragma unroll
            for (int i = 0; i < 2; i++) {
                int s = tid + 256 * i;
                int r = s >> 4, q = s & 15;
                *(uint4*)(buf + G1_A_OF + r * 272 + q * 16) = pa[i];
                int o = s >> 2, qq = s & 3;
                *(uint4*)(buf + G1_B_OF + o * 80 + qq * 16) = pw[i];
            }
        }
        __syncthreads();
    }

    #pragma unroll
    for (int mf = 0; mf < 2; mf++) {
        #pragma unroll
        for (int nf = 0; nf < 8; nf++) {
            size_t r0 = P0 + wm * 32 + mf * 16 + g;
            int col = jt * 128 + wn * 64 + nf * 8 + t2;
            *(float2*)&Out[r0 * C4 + col] = make_float2(acc[mf][nf][0], acc[mf][nf][1]);
            *(float2*)&Out[(r0 + 8) * C4 + col] = make_float2(acc[mf][nf][2], acc[mf][nf][3]);
        }
    }
}

// ==================================================================
// GEMM2 (mma.sync fp16, light loader, fused epilogue):
// T[p] = sum_o relu( (z @ W2^T)[p][o] + b2[o] ) * w3[o]
// A smem: [m=128][k=32] rows 80B; B smem: [o=128][k=32] rows 80B.
#define G2_A_OF 0
#define G2_B_OF 10240
#define G2_STAGE 20480
__global__ __launch_bounds__(256, 2) void gemm2_mma(const float* __restrict__ b2,
                                                    const float* __restrict__ w3) {
    extern __shared__ __align__(16) char sm2[];
    const int tid = threadIdx.x;
    const int wid = tid >> 5, lane = tid & 31;
    const int wm = wid & 3, wn = wid >> 2;
    const int g = lane >> 2, t2 = (lane & 3) * 2;
    const size_t P0 = (size_t)blockIdx.x * 128;
    const int roll = blockIdx.y;
    const __half* Z = (roll ? g_ZP : g_ZT) + P0 * C4;
    float* tOut = roll ? g_tP : g_tT;
    const uint32_t sb = smem_u32(sm2);

    float sAcc[4] = {0.f, 0.f, 0.f, 0.f};

    for (int nt = 0; nt < 8; nt++) {
        const int o0 = nt * 128;
        const __half* Wh = g_W2h + (size_t)o0 * C4;
        float acc[2][8][4];
        #pragma unroll
        for (int a = 0; a < 2; a++)
            #pragma unroll
            for (int b = 0; b < 8; b++)
                #pragma unroll
                for (int c = 0; c < 4; c++) acc[a][b][c] = 0.f;

        uint4 pa[2], pw[2];
        {
            #pragma unroll
            for (int i = 0; i < 2; i++) {
                int s = tid + 256 * i;
                int p = s >> 2, q = s & 3;
                pa[i] = *(const uint4*)(Z + (size_t)p * C4 + q * 8);
                pw[i] = *(const uint4*)(Wh + (size_t)p * C4 + q * 8);
            }
            char* buf = sm2;
            #pragma unroll
            for (int i = 0; i < 2; i++) {
                int s = tid + 256 * i;
                int p = s >> 2, q = s & 3;
                *(uint4*)(buf + G2_A_OF + p * 80 + q * 16) = pa[i];
                *(uint4*)(buf + G2_B_OF + p * 80 + q * 16) = pw[i];
            }
        }
        __syncthreads();

        for (int kc = 0; kc < 32; kc++) {
            if (kc + 1 < 32) {
                int k0 = (kc + 1) * 32;
                #pragma unroll
                for (int i = 0; i < 2; i++) {
                    int s = tid + 256 * i;
                    int p = s >> 2, q = s & 3;
                    pa[i] = *(const uint4*)(Z + (size_t)p * C4 + k0 + q * 8);
                    pw[i] = *(const uint4*)(Wh + (size_t)p * C4 + k0 + q * 8);
                }
            }
            const uint32_t base = sb + (kc & 1) * G2_STAGE;
            #pragma unroll
            for (int ks = 0; ks < 2; ks++) {
                uint32_t bh[8][2];
                #pragma unroll
                for (int np = 0; np < 4; np++) {
                    int row = wn * 64 + np * 16 + (lane & 7) + ((lane >> 4) & 1) * 8;
                    uint32_t col = ks * 32 + ((lane >> 3) & 1) * 16;
                    uint32_t a = base + G2_B_OF + row * 80 + col;
                    ldsm4(bh[2 * np][0], bh[2 * np][1], bh[2 * np + 1][0], bh[2 * np + 1][1], a);
                }
                #pragma unroll
                for (int mf = 0; mf < 2; mf++) {
                    int row = wm * 32 + mf * 16 + (lane & 7) + ((lane >> 3) & 1) * 8;
                    uint32_t col = ks * 32 + ((lane >> 4) & 1) * 16;
                    uint32_t a = base + G2_A_OF + row * 80 + col;
                    uint32_t a0, a1, a2, a3;
                    ldsm4(a0, a1, a2, a3, a);
                    #pragma unroll
                    for (int nf = 0; nf < 8; nf++)
                        mma_f16(acc[mf][nf], a0, a1, a2, a3, bh[nf][0], bh[nf][1]);
                }
            }
            if (kc + 1 < 32) {
                char* buf = sm2 + ((kc + 1) & 1) * G2_STAGE;
                #pragma unroll
                for (int i = 0; i < 2; i++) {
                    int s = tid + 256 * i;
                    int p = s >> 2, q = s & 3;
                    *(uint4*)(buf + G2_A_OF + p * 80 + q * 16) = pa[i];
                    *(uint4*)(buf + G2_B_OF + p * 80 + q * 16) = pw[i];
                }
            }
            __syncthreads();
        }

        // fold this o-tile into per-pixel scalars
        #pragma unroll
        for (int mf = 0; mf < 2; mf++) {
            #pragma unroll
            for (int nf = 0; nf < 8; nf++) {
                int c0 = o0 + wn * 64 + nf * 8 + t2;
                float b2a = __ldg(b2 + c0), b2b = __ldg(b2 + c0 + 1);
                float w3a = __ldg(w3 + c0), w3b = __ldg(w3 + c0 + 1);
                sAcc[mf * 2 + 0] += fmaxf(acc[mf][nf][0] + b2a, 0.f) * w3a
                                  + fmaxf(acc[mf][nf][1] + b2b, 0.f) * w3b;
                sAcc[mf * 2 + 1] += fmaxf(acc[mf][nf][2] + b2a, 0.f) * w3a
                                  + fmaxf(acc[mf][nf][3] + b2b, 0.f) * w3b;
            }
        }
    }

    // reduce across the 4-lane groups (same rows, different cols)
    #pragma unroll
    for (int i = 0; i < 4; i++) {
        sAcc[i] += __shfl_xor_sync(0xFFFFFFFFu, sAcc[i], 1);
        sAcc[i] += __shfl_xor_sync(0xFFFFFFFFu, sAcc[i], 2);
    }
    __syncthreads();
    float* sRed = (float*)sm2;   // reuse smem: [2][128]
    if ((lane & 3) == 0) {
        #pragma unroll
        for (int i = 0; i < 4; i++) {
            int r = wm * 32 + (i >> 1) * 16 + (i & 1) * 8 + g;
            sRed[wn * 128 + r] = sAcc[i];
        }
    }
    __syncthreads();
    if (tid < 128) tOut[P0 + tid] = sRed[tid] + sRed[128 + tid];
}

// ------------------------------------------------------------------
__global__ void loss_kernel(const float* __restrict__ st_b3, float* __restrict__ out) {
    __shared__ double red[256];
    int t = threadIdx.x;
    float b3 = st_b3[0];
    double s = 0.0;
    for (int i = t; i < NP; i += 256) {
        float tt = g_tT[i] + b3;
        float tp = g_tP[i] + b3;
        s += (double)softplusf(-tt) + (double)softplusf(tp);
    }
    red[t] = s;
    __syncthreads();
    for (int st = 128; st > 0; st >>= 1) { if (t < st) red[t] += red[t + st]; __syncthreads(); }
    if (t == 0) {
        out[LOSS_IDX] = (float)(red[0] / 81920.0);
        out[RATE_IDX] = (float)((double)g_cnt / 16777216.0);
    }
}

// ------------------------------------------------------------------
extern "C" void kernel_launch(void* const* d_in, const int* in_sizes, int n_in,
                              void* d_out, int out_size) {
    const float* feat     = (const float*)d_in[0];
    const float* mlp_w1   = (const float*)d_in[1];
    const float* mlp_w2   = (const float*)d_in[2];
    const float* sp_req_w = (const float*)d_in[3];
    const float* ch_fus_w = (const float*)d_in[4];
    const float* sp_fus_w = (const float*)d_in[5];
    const float* st_w1    = (const float*)d_in[6];
    const float* st_b1    = (const float*)d_in[7];
    const float* st_w2    = (const float*)d_in[8];
    const float* st_b2    = (const float*)d_in[9];
    const float* st_w3    = (const float*)d_in[10];
    const float* st_b3    = (const float*)d_in[11];

    float* out = (float*)d_out;
    float* out_sf = out;
    float* out_sm = out + SM_OFF;

    cudaFuncSetAttribute(gemm1_mma, cudaFuncAttributeMaxDynamicSharedMemorySize, 2 * G1_STAGE);
    cudaFuncSetAttribute(gemm2_mma, cudaFuncAttributeMaxDynamicSharedMemorySize, 2 * G2_STAGE);

    init_kernel<<<1, 32>>>();
    reduce_nc_kernel<<<N_IMG * C_CH, 256>>>(feat);
    reduce_pix_kernel<<<(NP + 255) / 256, 256>>>(feat);
    chatt_kernel<<<1, 256>>>(mlp_w1, mlp_w2);
    spatial_kernel<<<(NP + 255) / 256, 256>>>(sp_req_w);
    chcoef_kernel<<<1, 256>>>(ch_fus_w);
    spcoef_kernel<<<(4 * HW + 255) / 256, 256>>>(sp_fus_w);
    mask_kernel<<<2048, 256>>>(feat, out_sf, out_sm);

    w1h_kernel<<<(C4 * C2 + 255) / 256, 256>>>(st_w1);
    w2h_kernel<<<(C4 * C4 + 255) / 256, 256>>>(st_w2);

    dim3 g1grid(8, NP / 128, 2);
    gemm1_mma<<<g1grid, 256, 2 * G1_STAGE>>>();

    zprep_kernel<<<(int)(((size_t)NP * C4 / 4 + 255) / 256), 256>>>(st_b1);

    dim3 g2grid(NP / 128, 2);
    gemm2_mma<<<g2grid, 256, 2 * G2_STAGE>>>(st_b2, st_w3);

    loss_kernel<<<1, 256>>>(st_b3, out);
}